// round 4
// baseline (speedup 1.0000x reference)
#include <cuda_runtime.h>

// Problem constants (fixed by the reference): N=40000, F=64, H=64, E=1280000
#define MAXN 40000

// Scratch for segment sums (allocation-free: __device__ globals)
__device__ float g_agg[MAXN * 64];   // sum of m over edges per row-node
__device__ float g_aggc[MAXN * 3];   // sum of trans per row-node
__device__ float g_cnt[MAXN];        // edge count per row-node
__device__ int   g_idx64;            // 1 if edge_index buffer is int64, 0 if int32

__device__ __forceinline__ float silu(float x) {
    return __fdividef(x, 1.0f + __expf(-x));
}

// Detect edge_index dtype: for int64 values < 2^31 stored little-endian, every
// odd 32-bit word is zero. For int32 node ids in [0,40000), odd words are
// random ids (all-zero over 1024 samples has probability ~0).
__global__ void sniff_kernel(const int* __restrict__ ei32) {
    __shared__ int nonzero;
    if (threadIdx.x == 0) nonzero = 0;
    __syncthreads();
    for (int i = threadIdx.x; i < 1024; i += blockDim.x) {
        if (ei32[2 * i + 1] != 0) atomicOr(&nonzero, 1);
    }
    __syncthreads();
    if (threadIdx.x == 0) g_idx64 = (nonzero == 0) ? 1 : 0;
}

// Warp-level register-tiled GEMM fragment:
// each warp computes acc[8 rows][2 cols]; cols are (2*lane, 2*lane+1),
// rows are (eBase..eBase+7) of the 64-row tile held in shared Xs.
// Ws layout: [K][64] row-major. K = 4*K4.
template<int K4, int LDX>
__device__ __forceinline__ void gemm8x2(const float* __restrict__ Xs,
                                        const float* __restrict__ Ws,
                                        int eBase, int lane,
                                        float2 bias, float acc[8][2]) {
#pragma unroll
    for (int i = 0; i < 8; i++) { acc[i][0] = bias.x; acc[i][1] = bias.y; }
#pragma unroll 4
    for (int kc = 0; kc < K4; kc++) {
        const float* wr = Ws + (kc * 4) * 64 + 2 * lane;
        float2 w0 = *(const float2*)(wr);
        float2 w1 = *(const float2*)(wr + 64);
        float2 w2 = *(const float2*)(wr + 128);
        float2 w3 = *(const float2*)(wr + 192);
#pragma unroll
        for (int i = 0; i < 8; i++) {
            float4 x = *(const float4*)(Xs + (eBase + i) * LDX + kc * 4);
            acc[i][0] = fmaf(x.x, w0.x, fmaf(x.y, w1.x, fmaf(x.z, w2.x, fmaf(x.w, w3.x, acc[i][0]))));
            acc[i][1] = fmaf(x.x, w0.y, fmaf(x.y, w1.y, fmaf(x.z, w2.y, fmaf(x.w, w3.y, acc[i][1]))));
        }
    }
}

__global__ void zero_kernel(int n_nodes) {
    int idx = blockIdx.x * blockDim.x + threadIdx.x;
    int stride = gridDim.x * blockDim.x;
    for (int i = idx; i < n_nodes * 64; i += stride) g_agg[i] = 0.0f;
    for (int i = idx; i < n_nodes * 3; i += stride) g_aggc[i] = 0.0f;
    for (int i = idx; i < n_nodes; i += stride) g_cnt[i] = 0.0f;
}

// Shared layout sizes (floats) for the edge kernel
#define E_WE1   (129 * 64)      // 8256
#define E_WE2   4096
#define E_WC1   4096
#define E_EIN_LD 132            // padded row stride for [h_row|h_col|radial]

__global__ void __launch_bounds__(256)
edge_kernel(const float* __restrict__ h, const float* __restrict__ coord,
            const void* __restrict__ ei_raw, const float* __restrict__ emask,
            const float* __restrict__ We1, const float* __restrict__ be1,
            const float* __restrict__ We2, const float* __restrict__ be2,
            const float* __restrict__ Wc1, const float* __restrict__ bc1,
            const float* __restrict__ Wc2,
            int E, int N)
{
    extern __shared__ float sm[];
    float* We1s = sm;                       // 8256
    float* We2s = We1s + E_WE1;             // 4096
    float* Wc1s = We2s + E_WE2;             // 4096
    float* wc2s = Wc1s + E_WC1;             // 64
    float* be1s = wc2s + 64;                // 64
    float* be2s = be1s + 64;                // 64
    float* bc1s = be2s + 64;                // 64
    float* Ein  = bc1s + 64;                // 64*132
    float* Mb   = Ein + 64 * E_EIN_LD;      // 64*64
    float* sCd  = Mb + 64 * 64;             // 192
    float* sMk  = sCd + 192;                // 64
    int*   sRow = (int*)(sMk + 64);         // 64

    const long long* ei64 = (const long long*)ei_raw;
    const int*       ei32 = (const int*)ei_raw;
    const int is64 = g_idx64;

    int tid = threadIdx.x;
    for (int i = tid; i < E_WE1; i += 256) We1s[i] = We1[i];
    for (int i = tid; i < 4096; i += 256) { We2s[i] = We2[i]; Wc1s[i] = Wc1[i]; }
    if (tid < 64) {
        wc2s[tid] = Wc2[tid];
        be1s[tid] = be1[tid];
        be2s[tid] = be2[tid];
        bc1s[tid] = bc1[tid];
    }
    __syncthreads();

    int w = tid >> 5, lane = tid & 31;
    int eBase = w * 8;
    float2 b1 = *(float2*)&be1s[2 * lane];
    float2 b2 = *(float2*)&be2s[2 * lane];
    float2 b3 = *(float2*)&bc1s[2 * lane];
    float2 wc2v = *(float2*)&wc2s[2 * lane];

    const int numTiles = E / 64;   // E is a multiple of 64
    for (int tile = blockIdx.x; tile < numTiles; tile += gridDim.x) {
        int base = tile * 64;
        __syncthreads();  // protect prev-tile shared reads before overwrite

        // ---- stage: gather [h_row | h_col | radial] for 8 edges/warp ----
#pragma unroll
        for (int i = 0; i < 8; i++) {
            int el = eBase + i;
            long long e = (long long)base + el;
            int r, c;
            if (is64) {
                r = (int)ei64[e];
                c = (int)ei64[(long long)E + e];
            } else {
                r = ei32[e];
                c = ei32[(long long)E + e];
            }
            // safety clamp: a bad index becomes a wrong answer, not a crash
            r = min(max(r, 0), N - 1);
            c = min(max(c, 0), N - 1);
            *(float2*)&Ein[el * E_EIN_LD + 2 * lane]      = *(const float2*)&h[(long long)r * 64 + 2 * lane];
            *(float2*)&Ein[el * E_EIN_LD + 64 + 2 * lane] = *(const float2*)&h[(long long)c * 64 + 2 * lane];
            if (lane == 0) {
                float dx = coord[r * 3 + 0] - coord[c * 3 + 0];
                float dy = coord[r * 3 + 1] - coord[c * 3 + 1];
                float dz = coord[r * 3 + 2] - coord[c * 3 + 2];
                sCd[el * 3 + 0] = dx; sCd[el * 3 + 1] = dy; sCd[el * 3 + 2] = dz;
                Ein[el * E_EIN_LD + 128] = dx * dx + dy * dy + dz * dz;
                sRow[el] = r;
                sMk[el] = emask[e];
            }
        }
        __syncthreads();

        // ---- edge MLP layer 1: [64e x 129] @ [129 x 64] ----
        float acc[8][2];
        gemm8x2<32, E_EIN_LD>(Ein, We1s, eBase, lane, b1, acc);
        {   // radial term (k = 128)
            float2 w128 = *(float2*)&We1s[128 * 64 + 2 * lane];
#pragma unroll
            for (int i = 0; i < 8; i++) {
                float r = Ein[(eBase + i) * E_EIN_LD + 128];
                acc[i][0] = fmaf(r, w128.x, acc[i][0]);
                acc[i][1] = fmaf(r, w128.y, acc[i][1]);
            }
        }
#pragma unroll
        for (int i = 0; i < 8; i++) {
            float2 v = make_float2(silu(acc[i][0]), silu(acc[i][1]));
            *(float2*)&Mb[(eBase + i) * 64 + 2 * lane] = v;
        }
        __syncthreads();

        // ---- edge MLP layer 2: [64e x 64] @ [64 x 64], silu, mask ----
        gemm8x2<16, 64>(Mb, We2s, eBase, lane, b2, acc);
        float mf[8][2];
#pragma unroll
        for (int i = 0; i < 8; i++) {
            int el = eBase + i;
            float mk = sMk[el];
            mf[i][0] = silu(acc[i][0]) * mk;
            mf[i][1] = silu(acc[i][1]) * mk;
            int r = sRow[el];
            atomicAdd(&g_agg[(long long)r * 64 + 2 * lane],     mf[i][0]);
            atomicAdd(&g_agg[(long long)r * 64 + 2 * lane + 1], mf[i][1]);
            // stash masked m into Ein region (dead) for the coord MLP
            *(float2*)&Ein[el * E_EIN_LD + 2 * lane] = make_float2(mf[i][0], mf[i][1]);
        }
        __syncthreads();

        // ---- coord MLP: q = silu(m @ Wc1 + bc1); c = q . Wc2 ----
        gemm8x2<16, E_EIN_LD>(Ein, Wc1s, eBase, lane, b3, acc);
#pragma unroll
        for (int i = 0; i < 8; i++) {
            int el = eBase + i;
            float cp = silu(acc[i][0]) * wc2v.x + silu(acc[i][1]) * wc2v.y;
#pragma unroll
            for (int m = 16; m > 0; m >>= 1)
                cp += __shfl_xor_sync(0xffffffffu, cp, m);
            int r = sRow[el];
            if (lane < 3) {
                atomicAdd(&g_aggc[r * 3 + lane], sCd[el * 3 + lane] * cp * sMk[el]);
            } else if (lane == 3) {
                atomicAdd(&g_cnt[r], 1.0f);
            }
        }
    }
}

__global__ void __launch_bounds__(256)
node_kernel(const float* __restrict__ h, const float* __restrict__ coord,
            const float* __restrict__ Wn1, const float* __restrict__ bn1,
            const float* __restrict__ Wn2, const float* __restrict__ bn2,
            float* __restrict__ out, int N, long long out_size)
{
    extern __shared__ float sm[];
    float* W1s = sm;               // 128*64 = 8192
    float* W2s = W1s + 8192;       // 4096
    float* b1s = W2s + 4096;       // 64
    float* b2s = b1s + 64;         // 64
    float* Nin = b2s + 64;         // 64*128
    float* Hb  = Nin + 64 * 128;   // 64*64

    int tid = threadIdx.x;
    for (int i = tid; i < 8192; i += 256) W1s[i] = Wn1[i];
    for (int i = tid; i < 4096; i += 256) W2s[i] = Wn2[i];
    if (tid < 64) { b1s[tid] = bn1[tid]; b2s[tid] = bn2[tid]; }
    __syncthreads();

    int w = tid >> 5, lane = tid & 31;
    int nB = w * 8;
    float2 b1 = *(float2*)&b1s[2 * lane];
    float2 b2 = *(float2*)&b2s[2 * lane];

    float* hout = out;
    float* cout = out + (long long)N * 64;
    const bool has_coord_out = out_size >= (long long)N * 67;

    const int numTiles = N / 64;   // N is a multiple of 64 for N=40000? (40000/64=625) yes
    for (int tile = blockIdx.x; tile < numTiles; tile += gridDim.x) {
        int base = tile * 64;
        __syncthreads();
#pragma unroll
        for (int i = 0; i < 8; i++) {
            int nl = nB + i;
            int n = base + nl;
            *(float2*)&Nin[nl * 128 + 2 * lane]      = *(const float2*)&h[(long long)n * 64 + 2 * lane];
            *(float2*)&Nin[nl * 128 + 64 + 2 * lane] = *(const float2*)&g_agg[(long long)n * 64 + 2 * lane];
            if (lane < 3 && has_coord_out) {
                float cnt = fmaxf(g_cnt[n], 1.0f);
                cout[n * 3 + lane] = coord[n * 3 + lane] + g_aggc[n * 3 + lane] / cnt;
            }
        }
        __syncthreads();

        float acc[8][2];
        gemm8x2<32, 128>(Nin, W1s, nB, lane, b1, acc);
#pragma unroll
        for (int i = 0; i < 8; i++) {
            *(float2*)&Hb[(nB + i) * 64 + 2 * lane] =
                make_float2(silu(acc[i][0]), silu(acc[i][1]));
        }
        __syncthreads();

        gemm8x2<16, 64>(Hb, W2s, nB, lane, b2, acc);
#pragma unroll
        for (int i = 0; i < 8; i++) {
            int n = base + nB + i;
            *(float2*)&hout[(long long)n * 64 + 2 * lane] = make_float2(acc[i][0], acc[i][1]);
        }
    }
}

extern "C" void kernel_launch(void* const* d_in, const int* in_sizes, int n_in,
                              void* d_out, int out_size) {
    const float* h     = (const float*)d_in[0];
    const float* coord = (const float*)d_in[1];
    const void*  ei    = d_in[2];
    const float* emask = (const float*)d_in[3];
    const float* We1   = (const float*)d_in[4];
    const float* be1   = (const float*)d_in[5];
    const float* We2   = (const float*)d_in[6];
    const float* be2   = (const float*)d_in[7];
    const float* Wn1   = (const float*)d_in[8];
    const float* bn1   = (const float*)d_in[9];
    const float* Wn2   = (const float*)d_in[10];
    const float* bn2   = (const float*)d_in[11];
    const float* Wc1   = (const float*)d_in[12];
    const float* bc1   = (const float*)d_in[13];
    const float* Wc2   = (const float*)d_in[14];
    float* out = (float*)d_out;

    int N = in_sizes[0] / 64;   // 40000
    int E = in_sizes[3];        // 1280000 (edge_mask element count)

    size_t shE = (size_t)(E_WE1 + E_WE2 + E_WC1 + 64 * 4 +
                          64 * E_EIN_LD + 64 * 64 + 192 + 64 + 64) * sizeof(float);
    size_t shN = (size_t)(8192 + 4096 + 64 + 64 + 64 * 128 + 64 * 64) * sizeof(float);

    cudaFuncSetAttribute(edge_kernel, cudaFuncAttributeMaxDynamicSharedMemorySize, (int)shE);
    cudaFuncSetAttribute(node_kernel, cudaFuncAttributeMaxDynamicSharedMemorySize, (int)shN);

    sniff_kernel<<<1, 256>>>((const int*)ei);
    zero_kernel<<<512, 256>>>(N);
    edge_kernel<<<296, 256, shE>>>(h, coord, ei, emask,
                                   We1, be1, We2, be2, Wc1, bc1, Wc2, E, N);
    node_kernel<<<296, 256, shN>>>(h, coord, Wn1, bn1, Wn2, bn2, out, N,
                                   (long long)out_size);
}

// round 5
// speedup vs baseline: 1.8567x; 1.8567x over previous
#include <cuda_runtime.h>

// Problem constants (fixed by the reference): N=40000, F=64, H=64, E=1280000
#define MAXN 40000

// Scratch (allocation-free: __device__ globals)
__device__ float g_pre[MAXN * 128]; // [P_A (=h@We1_top + be1) | P_B (=h@We1_bot)]
__device__ float g_agg[MAXN * 64];  // sum of m over edges per row-node
__device__ float g_aggc[MAXN * 3];  // sum of trans per row-node
__device__ float g_cnt[MAXN];       // edge count per row-node
__device__ int   g_idx64;           // 1 if edge_index is int64, 0 if int32

typedef unsigned long long ull;

__device__ __forceinline__ float silu(float x) {
    return __fdividef(x, 1.0f + __expf(-x));
}
__device__ __forceinline__ ull pack2(float lo, float hi) {
    ull r; asm("mov.b64 %0, {%1, %2};" : "=l"(r) : "f"(lo), "f"(hi)); return r;
}
__device__ __forceinline__ float2 unpack2(ull v) {
    float2 f; asm("mov.b64 {%0, %1}, %2;" : "=f"(f.x), "=f"(f.y) : "l"(v)); return f;
}
__device__ __forceinline__ void fma2(ull& d, ull a, ull b) {
    asm("fma.rn.f32x2 %0, %1, %2, %3;" : "=l"(d) : "l"(a), "l"(b), "l"(d));
}

// ---------------- dtype sniff (int64 vs int32 edge_index) ----------------
__global__ void sniff_kernel(const int* __restrict__ ei32) {
    __shared__ int nonzero;
    if (threadIdx.x == 0) nonzero = 0;
    __syncthreads();
    for (int i = threadIdx.x; i < 1024; i += blockDim.x)
        if (ei32[2 * i + 1] != 0) atomicOr(&nonzero, 1);
    __syncthreads();
    if (threadIdx.x == 0) g_idx64 = (nonzero == 0) ? 1 : 0;
}

__global__ void zero_kernel(int n_nodes) {
    int idx = blockIdx.x * blockDim.x + threadIdx.x;
    int stride = gridDim.x * blockDim.x;
    for (int i = idx; i < n_nodes * 64; i += stride) g_agg[i] = 0.0f;
    for (int i = idx; i < n_nodes * 3; i += stride) g_aggc[i] = 0.0f;
    for (int i = idx; i < n_nodes; i += stride) g_cnt[i] = 0.0f;
}

// ---------------- scalar warp GEMM (small kernels) ----------------
// each warp: acc[8 rows][2 cols], cols (2*lane, 2*lane+1); Ws layout [K][64].
template<int K4, int LDX>
__device__ __forceinline__ void gemm8x2(const float* __restrict__ Xs,
                                        const float* __restrict__ Ws,
                                        int eBase, int lane,
                                        float2 bias, float acc[8][2]) {
#pragma unroll
    for (int i = 0; i < 8; i++) { acc[i][0] = bias.x; acc[i][1] = bias.y; }
#pragma unroll 4
    for (int kc = 0; kc < K4; kc++) {
        const float* wr = Ws + (kc * 4) * 64 + 2 * lane;
        float2 w0 = *(const float2*)(wr);
        float2 w1 = *(const float2*)(wr + 64);
        float2 w2 = *(const float2*)(wr + 128);
        float2 w3 = *(const float2*)(wr + 192);
#pragma unroll
        for (int i = 0; i < 8; i++) {
            float4 x = *(const float4*)(Xs + (eBase + i) * LDX + kc * 4);
            acc[i][0] = fmaf(x.x, w0.x, fmaf(x.y, w1.x, fmaf(x.z, w2.x, fmaf(x.w, w3.x, acc[i][0]))));
            acc[i][1] = fmaf(x.x, w0.y, fmaf(x.y, w1.y, fmaf(x.z, w2.y, fmaf(x.w, w3.y, acc[i][1]))));
        }
    }
}

// ---------------- packed f32x2 warp GEMM ----------------
// Xd: duplicated activation rows [v0,v0,v1,v1,...], row stride LDX (multiple of 4).
// acc[i] is a packed (c0,c1) pair, cols (2*lane, 2*lane+1).
template<int K4, int LDX>
__device__ __forceinline__ void gemmP(const float* __restrict__ Xd,
                                      const float* __restrict__ Ws,
                                      int lane, ull bias, ull acc[8]) {
#pragma unroll
    for (int i = 0; i < 8; i++) acc[i] = bias;
#pragma unroll 2
    for (int kc = 0; kc < K4; kc++) {
        const float* wr = Ws + (kc * 4) * 64 + 2 * lane;
        ull w0 = *(const ull*)(wr);
        ull w1 = *(const ull*)(wr + 64);
        ull w2 = *(const ull*)(wr + 128);
        ull w3 = *(const ull*)(wr + 192);
#pragma unroll
        for (int i = 0; i < 8; i++) {
            ulonglong2 xa = *(const ulonglong2*)(Xd + i * LDX + kc * 8);      // (vk,vk),(vk+1,vk+1)
            ulonglong2 xb = *(const ulonglong2*)(Xd + i * LDX + kc * 8 + 4);  // (vk+2..),(vk+3..)
            fma2(acc[i], xa.x, w0);
            fma2(acc[i], xa.y, w1);
            fma2(acc[i], xb.x, w2);
            fma2(acc[i], xb.y, w3);
        }
    }
}

// ---------------- per-node precompute: P = [h@We1_top + be1 | h@We1_bot] ----------------
__global__ void __launch_bounds__(256)
pre_kernel(const float* __restrict__ h, const float* __restrict__ We1,
           const float* __restrict__ be1, int N)
{
    extern __shared__ float sm[];
    float* WA   = sm;            // 4096 (We1 rows 0..63)
    float* WB   = WA + 4096;     // 4096 (We1 rows 64..127)
    float* be1s = WB + 4096;     // 64
    float* Ht   = be1s + 64;     // 64*68

    int tid = threadIdx.x;
    for (int i = tid; i < 4096; i += 256) { WA[i] = We1[i]; WB[i] = We1[4096 + i]; }
    if (tid < 64) be1s[tid] = be1[tid];
    __syncthreads();

    int w = tid >> 5, lane = tid & 31;
    int rB = w * 8;
    float2 b1 = *(float2*)&be1s[2 * lane];
    float2 z2 = make_float2(0.0f, 0.0f);

    const int numTiles = N / 64;   // 625
    for (int tile = blockIdx.x; tile < numTiles; tile += gridDim.x) {
        int base = tile * 64;
        __syncthreads();
#pragma unroll
        for (int i = 0; i < 8; i++) {
            int n = base + rB + i;
            *(float2*)&Ht[(rB + i) * 68 + 2 * lane] = *(const float2*)&h[(long long)n * 64 + 2 * lane];
        }
        __syncthreads();

        float accA[8][2], accB[8][2];
        gemm8x2<16, 68>(Ht, WA, rB, lane, b1, accA);
        gemm8x2<16, 68>(Ht, WB, rB, lane, z2, accB);
#pragma unroll
        for (int i = 0; i < 8; i++) {
            int n = base + rB + i;
            *(float2*)&g_pre[n * 128 + 2 * lane]      = make_float2(accA[i][0], accA[i][1]);
            *(float2*)&g_pre[n * 128 + 64 + 2 * lane] = make_float2(accB[i][0], accB[i][1]);
        }
    }
}

// ---------------- edge kernel: warp-autonomous, f32x2 GEMMs ----------------
// shared: We2s[4096] Wc1s[4096] w128s[64] be2s[64] bc1s[64] wc2s[64]
//         Md: 8 warps x (8 rows x 136 dup floats) = 8704
//         meta: 8 warps x 64
#define SM_MD    8448
#define SM_META  17152
#define SM_EDGE_FLOATS 17664

__global__ void __launch_bounds__(256, 3)
edge_kernel2(const float* __restrict__ coord,
             const void* __restrict__ ei_raw, const float* __restrict__ emask,
             const float* __restrict__ We1, const float* __restrict__ We2,
             const float* __restrict__ be2, const float* __restrict__ Wc1,
             const float* __restrict__ bc1, const float* __restrict__ Wc2,
             int E, int N)
{
    extern __shared__ float sm[];
    float* We2s = sm;            // 4096
    float* Wc1s = sm + 4096;     // 4096
    float* w128s = sm + 8192;    // 64
    float* be2s = sm + 8256;     // 64
    float* bc1s = sm + 8320;     // 64
    float* wc2s = sm + 8384;     // 64

    const long long* ei64 = (const long long*)ei_raw;
    const int*       ei32 = (const int*)ei_raw;
    const int is64 = g_idx64;

    int tid = threadIdx.x;
    for (int i = tid; i < 4096; i += 256) { We2s[i] = We2[i]; Wc1s[i] = Wc1[i]; }
    if (tid < 64) {
        w128s[tid] = We1[128 * 64 + tid];
        be2s[tid] = be2[tid];
        bc1s[tid] = bc1[tid];
        wc2s[tid] = Wc2[tid];
    }
    __syncthreads();

    int w = tid >> 5, lane = tid & 31;
    float* Md   = sm + SM_MD + w * 1088;      // 8 rows x 136
    float* meta = sm + SM_META + w * 64;
    int*   sRow = (int*)meta;                 // 8
    int*   sCol = (int*)(meta + 8);           // 8
    float* sMk  = meta + 16;                  // 8
    float* sRad = meta + 24;                  // 8
    float* sCd  = meta + 32;                  // 24

    ull b2p  = pack2(be2s[2 * lane], be2s[2 * lane + 1]);
    ull bc1p = pack2(bc1s[2 * lane], bc1s[2 * lane + 1]);
    float2 w128p = *(float2*)&w128s[2 * lane];
    float2 wc2p  = *(float2*)&wc2s[2 * lane];

    const int nG = E / 8;  // 8 edges per warp-group
    for (int g = blockIdx.x * 8 + w; g < nG; g += gridDim.x * 8) {
        int base = g * 8;

        // ---- stage meta (8 edges, lanes 0..7) ----
        if (lane < 8) {
            long long e = (long long)base + lane;
            int r, c;
            if (is64) { r = (int)ei64[e]; c = (int)ei64[(long long)E + e]; }
            else      { r = ei32[e];      c = ei32[(long long)E + e]; }
            r = min(max(r, 0), N - 1);
            c = min(max(c, 0), N - 1);
            sRow[lane] = r; sCol[lane] = c;
            float dx = coord[r * 3 + 0] - coord[c * 3 + 0];
            float dy = coord[r * 3 + 1] - coord[c * 3 + 1];
            float dz = coord[r * 3 + 2] - coord[c * 3 + 2];
            sCd[lane * 3 + 0] = dx; sCd[lane * 3 + 1] = dy; sCd[lane * 3 + 2] = dz;
            sRad[lane] = dx * dx + dy * dy + dz * dz;
            sMk[lane] = emask[e];
        }
        __syncwarp();

        // ---- combine precomputed layer-1: m1 = silu(PA[r] + PB[c] + radial*w128) ----
#pragma unroll
        for (int i = 0; i < 8; i++) {
            int r = sRow[i], c = sCol[i];
            float2 pa = *(const float2*)&g_pre[r * 128 + 2 * lane];
            float2 pb = *(const float2*)&g_pre[c * 128 + 64 + 2 * lane];
            float rad = sRad[i];
            float m0 = silu(fmaf(rad, w128p.x, pa.x + pb.x));
            float m1 = silu(fmaf(rad, w128p.y, pa.y + pb.y));
            *(float4*)&Md[i * 136 + 4 * lane] = make_float4(m0, m0, m1, m1);
        }
        __syncwarp();

        // ---- layer 2: m = silu(m1 @ We2 + be2) * mask ----
        ull acc[8];
        gemmP<16, 136>(Md, We2s, lane, b2p, acc);
        __syncwarp();  // all Md reads complete before in-place overwrite
#pragma unroll
        for (int i = 0; i < 8; i++) {
            float2 v = unpack2(acc[i]);
            float mk = sMk[i];
            float mm0 = silu(v.x) * mk;
            float mm1 = silu(v.y) * mk;
            *(float4*)&Md[i * 136 + 4 * lane] = make_float4(mm0, mm0, mm1, mm1);
            int r = sRow[i];
            atomicAdd(&g_agg[r * 64 + 2 * lane],     mm0);
            atomicAdd(&g_agg[r * 64 + 2 * lane + 1], mm1);
        }
        __syncwarp();

        // ---- coord MLP: cp = silu(m @ Wc1 + bc1) . Wc2 ----
        gemmP<16, 136>(Md, Wc1s, lane, bc1p, acc);
#pragma unroll
        for (int i = 0; i < 8; i++) {
            float2 q = unpack2(acc[i]);
            float s = silu(q.x) * wc2p.x + silu(q.y) * wc2p.y;
#pragma unroll
            for (int m = 16; m > 0; m >>= 1)
                s += __shfl_xor_sync(0xffffffffu, s, m);
            int r = sRow[i];
            if (lane < 3) {
                atomicAdd(&g_aggc[r * 3 + lane], sCd[i * 3 + lane] * s * sMk[i]);
            } else if (lane == 3) {
                atomicAdd(&g_cnt[r], 1.0f);
            }
        }
        __syncwarp();  // protect Md/meta reuse across iterations
    }
}

// ---------------- node kernel (unchanged from passing R4) ----------------
__global__ void __launch_bounds__(256)
node_kernel(const float* __restrict__ h, const float* __restrict__ coord,
            const float* __restrict__ Wn1, const float* __restrict__ bn1,
            const float* __restrict__ Wn2, const float* __restrict__ bn2,
            float* __restrict__ out, int N, long long out_size)
{
    extern __shared__ float sm[];
    float* W1s = sm;               // 128*64 = 8192
    float* W2s = W1s + 8192;       // 4096
    float* b1s = W2s + 4096;       // 64
    float* b2s = b1s + 64;         // 64
    float* Nin = b2s + 64;         // 64*128
    float* Hb  = Nin + 64 * 128;   // 64*64

    int tid = threadIdx.x;
    for (int i = tid; i < 8192; i += 256) W1s[i] = Wn1[i];
    for (int i = tid; i < 4096; i += 256) W2s[i] = Wn2[i];
    if (tid < 64) { b1s[tid] = bn1[tid]; b2s[tid] = bn2[tid]; }
    __syncthreads();

    int w = tid >> 5, lane = tid & 31;
    int nB = w * 8;
    float2 b1 = *(float2*)&b1s[2 * lane];
    float2 b2 = *(float2*)&b2s[2 * lane];

    float* hout = out;
    float* cout = out + (long long)N * 64;
    const bool has_coord_out = out_size >= (long long)N * 67;

    const int numTiles = N / 64;
    for (int tile = blockIdx.x; tile < numTiles; tile += gridDim.x) {
        int base = tile * 64;
        __syncthreads();
#pragma unroll
        for (int i = 0; i < 8; i++) {
            int nl = nB + i;
            int n = base + nl;
            *(float2*)&Nin[nl * 128 + 2 * lane]      = *(const float2*)&h[(long long)n * 64 + 2 * lane];
            *(float2*)&Nin[nl * 128 + 64 + 2 * lane] = *(const float2*)&g_agg[(long long)n * 64 + 2 * lane];
            if (lane < 3 && has_coord_out) {
                float cnt = fmaxf(g_cnt[n], 1.0f);
                cout[n * 3 + lane] = coord[n * 3 + lane] + g_aggc[n * 3 + lane] / cnt;
            }
        }
        __syncthreads();

        float acc[8][2];
        gemm8x2<32, 128>(Nin, W1s, nB, lane, b1, acc);
#pragma unroll
        for (int i = 0; i < 8; i++) {
            *(float2*)&Hb[(nB + i) * 64 + 2 * lane] =
                make_float2(silu(acc[i][0]), silu(acc[i][1]));
        }
        __syncthreads();

        gemm8x2<16, 64>(Hb, W2s, nB, lane, b2, acc);
#pragma unroll
        for (int i = 0; i < 8; i++) {
            int n = base + nB + i;
            *(float2*)&hout[(long long)n * 64 + 2 * lane] = make_float2(acc[i][0], acc[i][1]);
        }
    }
}

extern "C" void kernel_launch(void* const* d_in, const int* in_sizes, int n_in,
                              void* d_out, int out_size) {
    const float* h     = (const float*)d_in[0];
    const float* coord = (const float*)d_in[1];
    const void*  ei    = d_in[2];
    const float* emask = (const float*)d_in[3];
    const float* We1   = (const float*)d_in[4];
    const float* be1   = (const float*)d_in[5];
    const float* We2   = (const float*)d_in[6];
    const float* be2   = (const float*)d_in[7];
    const float* Wn1   = (const float*)d_in[8];
    const float* bn1   = (const float*)d_in[9];
    const float* Wn2   = (const float*)d_in[10];
    const float* bn2   = (const float*)d_in[11];
    const float* Wc1   = (const float*)d_in[12];
    const float* bc1   = (const float*)d_in[13];
    const float* Wc2   = (const float*)d_in[14];
    float* out = (float*)d_out;

    int N = in_sizes[0] / 64;   // 40000
    int E = in_sizes[3];        // 1280000

    size_t shP = (size_t)(4096 + 4096 + 64 + 64 * 68) * sizeof(float);
    size_t shE = (size_t)SM_EDGE_FLOATS * sizeof(float);
    size_t shN = (size_t)(8192 + 4096 + 64 + 64 + 64 * 128 + 64 * 64) * sizeof(float);

    cudaFuncSetAttribute(pre_kernel,  cudaFuncAttributeMaxDynamicSharedMemorySize, (int)shP);
    cudaFuncSetAttribute(edge_kernel2, cudaFuncAttributeMaxDynamicSharedMemorySize, (int)shE);
    cudaFuncSetAttribute(node_kernel, cudaFuncAttributeMaxDynamicSharedMemorySize, (int)shN);

    sniff_kernel<<<1, 256>>>((const int*)ei);
    zero_kernel<<<512, 256>>>(N);
    pre_kernel<<<625, 256, shP>>>(h, We1, be1, N);
    edge_kernel2<<<444, 256, shE>>>(coord, ei, emask,
                                    We1, We2, be2, Wc1, bc1, Wc2, E, N);
    node_kernel<<<296, 256, shN>>>(h, coord, Wn1, bn1, Wn2, bn2, out, N,
                                   (long long)out_size);
}

// round 6
// speedup vs baseline: 2.2074x; 1.1889x over previous
#include <cuda_runtime.h>

// Problem constants: N=40000, F=64, H=64, E=1280000
#define MAXN 40000

__device__ float g_pre[MAXN * 128]; // [P_A = h@We1_top + be1 | P_B = h@We1_bot]
__device__ float g_agg[MAXN * 64];  // sum of m per row-node
__device__ float g_aggc[MAXN * 3];  // sum of trans per row-node
__device__ float g_cnt[MAXN];       // edge count per row-node
__device__ int   g_idx64;           // edge_index dtype flag

typedef unsigned long long ull;

__device__ __forceinline__ float silu(float x) {
    return __fdividef(x, 1.0f + __expf(-x));
}
__device__ __forceinline__ ull pack2(float lo, float hi) {
    ull r; asm("mov.b64 %0, {%1, %2};" : "=l"(r) : "f"(lo), "f"(hi)); return r;
}
__device__ __forceinline__ float2 unpack2(ull v) {
    float2 f; asm("mov.b64 {%0, %1}, %2;" : "=f"(f.x), "=f"(f.y) : "l"(v)); return f;
}
__device__ __forceinline__ void fma2(ull& d, ull a, ull b) {
    asm("fma.rn.f32x2 %0, %1, %2, %3;" : "=l"(d) : "l"(a), "l"(b), "l"(d));
}
__device__ __forceinline__ float fin(ull a) { float2 u = unpack2(a); return u.x + u.y; }

// ---------------- dtype sniff ----------------
__global__ void sniff_kernel(const int* __restrict__ ei32) {
    __shared__ int nonzero;
    if (threadIdx.x == 0) nonzero = 0;
    __syncthreads();
    for (int i = threadIdx.x; i < 1024; i += blockDim.x)
        if (ei32[2 * i + 1] != 0) atomicOr(&nonzero, 1);
    __syncthreads();
    if (threadIdx.x == 0) g_idx64 = (nonzero == 0) ? 1 : 0;
}

__global__ void zero_kernel(int n_nodes) {
    int idx = blockIdx.x * blockDim.x + threadIdx.x;
    int stride = gridDim.x * blockDim.x;
    for (int i = idx; i < n_nodes * 64; i += stride) g_agg[i] = 0.0f;
    for (int i = idx; i < n_nodes * 3; i += stride) g_aggc[i] = 0.0f;
    for (int i = idx; i < n_nodes; i += stride) g_cnt[i] = 0.0f;
}

// ---------------- transposed weight staging ----------------
// W: [K][64] row-major in gmem. Wt tile (j = k-pair, lane = col-pair):
// Wt[j*128 + l*4 + {0..3}] = { W[2j][2l], W[2j+1][2l], W[2j][2l+1], W[2j+1][2l+1] }
__device__ __forceinline__ void stage_wt(float* dst, const float* __restrict__ W,
                                         int elems, int tid, int nt) {
    for (int i = tid; i < elems; i += nt) {
        int j = i >> 7, rem = i & 127, l = rem >> 2, s = rem & 3;
        dst[i] = W[(2 * j + (s & 1)) * 64 + 2 * l + (s >> 1)];
    }
}

// ---------------- k-pair packed GEMM ----------------
// Xs: undup activations, row stride LDX (16B-aligned rows). Wt as above.
// Lane computes cols (2*lane, 2*lane+1); result = fin(acc) (even/odd-k halves).
template<int K4, int ROWS, int LDX>
__device__ __forceinline__ void gemmPK(const float* __restrict__ Xs,
                                       const float* __restrict__ Wt,
                                       int lane, ull bi0, ull bi1,
                                       ull acc0[ROWS], ull acc1[ROWS]) {
#pragma unroll
    for (int i = 0; i < ROWS; i++) { acc0[i] = bi0; acc1[i] = bi1; }
#pragma unroll 2
    for (int kc = 0; kc < K4; kc++) {
        const float* wp = Wt + kc * 256 + lane * 4;
        ulonglong2 wa = *(const ulonglong2*)(wp);        // j = 2kc
        ulonglong2 wb = *(const ulonglong2*)(wp + 128);  // j = 2kc+1
#pragma unroll
        for (int i = 0; i < ROWS; i++) {
            ulonglong2 xv = *(const ulonglong2*)(Xs + i * LDX + kc * 4);
            fma2(acc0[i], xv.x, wa.x);
            fma2(acc1[i], xv.x, wa.y);
            fma2(acc0[i], xv.y, wb.x);
            fma2(acc1[i], xv.y, wb.y);
        }
    }
}

// ---------------- per-node precompute ----------------
// smem: WAt 4096 | WBt 4096 | be1s 64 | Ht 8*512
__global__ void __launch_bounds__(256)
pre_kernel(const float* __restrict__ h, const float* __restrict__ We1,
           const float* __restrict__ be1, int N)
{
    extern __shared__ float sm[];
    float* WAt  = sm;
    float* WBt  = sm + 4096;
    float* be1s = sm + 8192;
    float* HtA  = sm + 8256;

    int tid = threadIdx.x;
    stage_wt(WAt, We1, 4096, tid, 256);
    stage_wt(WBt, We1 + 4096, 4096, tid, 256);
    if (tid < 64) be1s[tid] = be1[tid];
    __syncthreads();

    int w = tid >> 5, lane = tid & 31;
    float* Ht = HtA + w * 512;
    ull b0 = pack2(be1s[2 * lane], 0.0f);
    ull b1 = pack2(be1s[2 * lane + 1], 0.0f);
    ull z = pack2(0.0f, 0.0f);

    const int nGp = N / 8;   // 5000
    for (int g = blockIdx.x * 8 + w; g < nGp; g += gridDim.x * 8) {
        int base = g * 8;
        __syncwarp();
#pragma unroll
        for (int i = 0; i < 8; i++)
            *(float2*)&Ht[i * 64 + 2 * lane] = *(const float2*)&h[(base + i) * 64 + 2 * lane];
        __syncwarp();

        ull a0[8], a1[8];
        gemmPK<16, 8, 64>(Ht, WAt, lane, b0, b1, a0, a1);
#pragma unroll
        for (int i = 0; i < 8; i++)
            *(float2*)&g_pre[(base + i) * 128 + 2 * lane] = make_float2(fin(a0[i]), fin(a1[i]));
        gemmPK<16, 8, 64>(Ht, WBt, lane, z, z, a0, a1);
#pragma unroll
        for (int i = 0; i < 8; i++)
            *(float2*)&g_pre[(base + i) * 128 + 64 + 2 * lane] = make_float2(fin(a0[i]), fin(a1[i]));
    }
}

// ---------------- edge kernel ----------------
#define EROWS 16
// smem floats: We2t 4096 | Wc1t 4096 | w128s 64 | be2s 64 | bc1s 64 | wc2s 64
//              Md 8*1024 | meta 8*128  => 17664
__global__ void __launch_bounds__(256, 2)
edge_kernel3(const float* __restrict__ coord,
             const void* __restrict__ ei_raw, const float* __restrict__ emask,
             const float* __restrict__ We1, const float* __restrict__ We2,
             const float* __restrict__ be2, const float* __restrict__ Wc1,
             const float* __restrict__ bc1, const float* __restrict__ Wc2,
             int E, int N)
{
    extern __shared__ float sm[];
    float* We2t = sm;
    float* Wc1t = sm + 4096;
    float* w128s = sm + 8192;
    float* be2s = sm + 8256;
    float* bc1s = sm + 8320;
    float* wc2s = sm + 8384;
    float* MdA  = sm + 8448;
    float* metaA = sm + 16640;

    const long long* ei64 = (const long long*)ei_raw;
    const int*       ei32 = (const int*)ei_raw;
    const int is64 = g_idx64;

    int tid = threadIdx.x;
    stage_wt(We2t, We2, 4096, tid, 256);
    stage_wt(Wc1t, Wc1, 4096, tid, 256);
    if (tid < 64) {
        w128s[tid] = We1[128 * 64 + tid];
        be2s[tid] = be2[tid];
        bc1s[tid] = bc1[tid];
        wc2s[tid] = Wc2[tid];
    }
    __syncthreads();

    int w = tid >> 5, lane = tid & 31;
    float* Md   = MdA + w * 1024;            // 16 rows x 64
    float* meta = metaA + w * 128;
    int*   sRow = (int*)meta;                // 16
    int*   sCol = (int*)(meta) + 16;         // 16
    float* sMk  = meta + 32;                 // 16
    float* sRad = meta + 48;                 // 16
    float* sCd  = meta + 64;                 // 48

    ull b20 = pack2(be2s[2 * lane], 0.0f);
    ull b21 = pack2(be2s[2 * lane + 1], 0.0f);
    ull bc0 = pack2(bc1s[2 * lane], 0.0f);
    ull bc1p = pack2(bc1s[2 * lane + 1], 0.0f);
    float2 w128p = *(float2*)&w128s[2 * lane];
    float2 wc2p  = *(float2*)&wc2s[2 * lane];

    const int nG = E / EROWS;   // 80000
    for (int g = blockIdx.x * 8 + w; g < nG; g += gridDim.x * 8) {
        int base = g * EROWS;
        __syncwarp();  // protect prev-iteration meta/Md reads

        // ---- meta (lanes 0..15, one edge each) ----
        if (lane < EROWS) {
            long long e = (long long)base + lane;
            int r, c;
            if (is64) { r = (int)ei64[e]; c = (int)ei64[(long long)E + e]; }
            else      { r = ei32[e];      c = ei32[(long long)E + e]; }
            r = min(max(r, 0), N - 1);
            c = min(max(c, 0), N - 1);
            sRow[lane] = r; sCol[lane] = c;
            float dx = coord[r * 3 + 0] - coord[c * 3 + 0];
            float dy = coord[r * 3 + 1] - coord[c * 3 + 1];
            float dz = coord[r * 3 + 2] - coord[c * 3 + 2];
            sCd[lane * 3 + 0] = dx; sCd[lane * 3 + 1] = dy; sCd[lane * 3 + 2] = dz;
            sRad[lane] = dx * dx + dy * dy + dz * dz;
            sMk[lane] = emask[e];
        }
        __syncwarp();

        // ---- combine precomputed layer-1 ----
#pragma unroll
        for (int i = 0; i < EROWS; i++) {
            int r = sRow[i], c = sCol[i];
            float2 pa = *(const float2*)&g_pre[r * 128 + 2 * lane];
            float2 pb = *(const float2*)&g_pre[c * 128 + 64 + 2 * lane];
            float rad = sRad[i];
            float m0 = silu(fmaf(rad, w128p.x, pa.x + pb.x));
            float m1 = silu(fmaf(rad, w128p.y, pa.y + pb.y));
            *(float2*)&Md[i * 64 + 2 * lane] = make_float2(m0, m1);
        }
        __syncwarp();

        // ---- layer 2: m = silu(m1 @ We2 + be2) * mask ----
        ull a0[EROWS], a1[EROWS];
        gemmPK<16, EROWS, 64>(Md, We2t, lane, b20, b21, a0, a1);
        __syncwarp();  // all Md reads done before overwrite
#pragma unroll
        for (int i = 0; i < EROWS; i++) {
            float mk = sMk[i];
            float mm0 = silu(fin(a0[i])) * mk;
            float mm1 = silu(fin(a1[i])) * mk;
            *(float2*)&Md[i * 64 + 2 * lane] = make_float2(mm0, mm1);
            asm volatile("red.global.add.v2.f32 [%0], {%1, %2};"
                         :: "l"(g_agg + sRow[i] * 64 + 2 * lane), "f"(mm0), "f"(mm1)
                         : "memory");
        }
        __syncwarp();

        // ---- coord MLP: cp = silu(m @ Wc1 + bc1) . Wc2 ----
        gemmPK<16, EROWS, 64>(Md, Wc1t, lane, bc0, bc1p, a0, a1);
#pragma unroll
        for (int i = 0; i < EROWS; i++) {
            float s = silu(fin(a0[i])) * wc2p.x + silu(fin(a1[i])) * wc2p.y;
#pragma unroll
            for (int m = 16; m > 0; m >>= 1)
                s += __shfl_xor_sync(0xffffffffu, s, m);
            int r = sRow[i];
            if (lane < 3) {
                atomicAdd(&g_aggc[r * 3 + lane], sCd[i * 3 + lane] * s * sMk[i]);
            } else if (lane == 3) {
                atomicAdd(&g_cnt[r], 1.0f);
            }
        }
    }
}

// ---------------- node kernel ----------------
// smem floats: W1t 8192 | W2t 4096 | b1s 64 | b2s 64 | Nin 8*1024 | Hb 8*512
__global__ void __launch_bounds__(256)
node_kernel(const float* __restrict__ h, const float* __restrict__ coord,
            const float* __restrict__ Wn1, const float* __restrict__ bn1,
            const float* __restrict__ Wn2, const float* __restrict__ bn2,
            float* __restrict__ out, int N, long long out_size)
{
    extern __shared__ float sm[];
    float* W1t = sm;                // 8192 (K=128)
    float* W2t = sm + 8192;         // 4096
    float* b1s = sm + 12288;
    float* b2s = sm + 12352;
    float* NinA = sm + 12416;       // 8*1024
    float* HbA  = sm + 20608;       // 8*512

    int tid = threadIdx.x;
    stage_wt(W1t, Wn1, 8192, tid, 256);
    stage_wt(W2t, Wn2, 4096, tid, 256);
    if (tid < 64) { b1s[tid] = bn1[tid]; b2s[tid] = bn2[tid]; }
    __syncthreads();

    int w = tid >> 5, lane = tid & 31;
    float* Nin = NinA + w * 1024;   // 8 rows x 128
    float* Hb  = HbA + w * 512;     // 8 rows x 64
    ull b10 = pack2(b1s[2 * lane], 0.0f);
    ull b11 = pack2(b1s[2 * lane + 1], 0.0f);
    ull b20 = pack2(b2s[2 * lane], 0.0f);
    ull b21 = pack2(b2s[2 * lane + 1], 0.0f);

    float* hout = out;
    float* cout = out + (long long)N * 64;
    const bool has_coord_out = out_size >= (long long)N * 67;

    const int nGp = N / 8;   // 5000
    for (int g = blockIdx.x * 8 + w; g < nGp; g += gridDim.x * 8) {
        int base = g * 8;
        __syncwarp();
#pragma unroll
        for (int i = 0; i < 8; i++) {
            int n = base + i;
            *(float2*)&Nin[i * 128 + 2 * lane]      = *(const float2*)&h[(long long)n * 64 + 2 * lane];
            *(float2*)&Nin[i * 128 + 64 + 2 * lane] = *(const float2*)&g_agg[(long long)n * 64 + 2 * lane];
            if (lane < 3 && has_coord_out) {
                float cnt = fmaxf(g_cnt[n], 1.0f);
                cout[n * 3 + lane] = coord[n * 3 + lane] + g_aggc[n * 3 + lane] / cnt;
            }
        }
        __syncwarp();

        ull a0[8], a1[8];
        gemmPK<32, 8, 128>(Nin, W1t, lane, b10, b11, a0, a1);
        __syncwarp();
#pragma unroll
        for (int i = 0; i < 8; i++)
            *(float2*)&Hb[i * 64 + 2 * lane] = make_float2(silu(fin(a0[i])), silu(fin(a1[i])));
        __syncwarp();

        gemmPK<16, 8, 64>(Hb, W2t, lane, b20, b21, a0, a1);
#pragma unroll
        for (int i = 0; i < 8; i++) {
            int n = base + i;
            *(float2*)&hout[(long long)n * 64 + 2 * lane] = make_float2(fin(a0[i]), fin(a1[i]));
        }
    }
}

extern "C" void kernel_launch(void* const* d_in, const int* in_sizes, int n_in,
                              void* d_out, int out_size) {
    const float* h     = (const float*)d_in[0];
    const float* coord = (const float*)d_in[1];
    const void*  ei    = d_in[2];
    const float* emask = (const float*)d_in[3];
    const float* We1   = (const float*)d_in[4];
    const float* be1   = (const float*)d_in[5];
    const float* We2   = (const float*)d_in[6];
    const float* be2   = (const float*)d_in[7];
    const float* Wn1   = (const float*)d_in[8];
    const float* bn1   = (const float*)d_in[9];
    const float* Wn2   = (const float*)d_in[10];
    const float* bn2   = (const float*)d_in[11];
    const float* Wc1   = (const float*)d_in[12];
    const float* bc1   = (const float*)d_in[13];
    const float* Wc2   = (const float*)d_in[14];
    float* out = (float*)d_out;

    int N = in_sizes[0] / 64;   // 40000
    int E = in_sizes[3];        // 1280000

    size_t shP = (size_t)(4096 + 4096 + 64 + 8 * 512) * sizeof(float);
    size_t shE = (size_t)17664 * sizeof(float);
    size_t shN = (size_t)(8192 + 4096 + 64 + 64 + 8 * 1024 + 8 * 512) * sizeof(float);

    cudaFuncSetAttribute(pre_kernel,   cudaFuncAttributeMaxDynamicSharedMemorySize, (int)shP);
    cudaFuncSetAttribute(edge_kernel3, cudaFuncAttributeMaxDynamicSharedMemorySize, (int)shE);
    cudaFuncSetAttribute(node_kernel,  cudaFuncAttributeMaxDynamicSharedMemorySize, (int)shN);

    sniff_kernel<<<1, 256>>>((const int*)ei);
    zero_kernel<<<512, 256>>>(N);
    pre_kernel<<<296, 256, shP>>>(h, We1, be1, N);
    edge_kernel3<<<296, 256, shE>>>(coord, ei, emask,
                                    We1, We2, be2, Wc1, bc1, Wc2, E, N);
    node_kernel<<<296, 256, shN>>>(h, coord, Wn1, bn1, Wn2, bn2, out, N,
                                   (long long)out_size);
}

// round 7
// speedup vs baseline: 2.2767x; 1.0314x over previous
#include <cuda_runtime.h>

// Problem constants: N=40000, F=64, H=64, E=1280000
#define MAXN 40000

__device__ float g_pre[MAXN * 128]; // [P_A = h@We1_top + be1 | P_B = h@We1_bot]
__device__ float g_agg[MAXN * 64];  // sum of m per row-node
__device__ float g_aggc[MAXN * 3];  // sum of trans per row-node
__device__ float g_cnt[MAXN];       // edge count per row-node
__device__ int   g_idx64;           // edge_index dtype flag

typedef unsigned long long ull;

__device__ __forceinline__ float silu(float x) {
    return __fdividef(x, 1.0f + __expf(-x));
}
__device__ __forceinline__ ull pack2(float lo, float hi) {
    ull r; asm("mov.b64 %0, {%1, %2};" : "=l"(r) : "f"(lo), "f"(hi)); return r;
}
__device__ __forceinline__ float2 unpack2(ull v) {
    float2 f; asm("mov.b64 {%0, %1}, %2;" : "=f"(f.x), "=f"(f.y) : "l"(v)); return f;
}
__device__ __forceinline__ void fma2(ull& d, ull a, ull b) {
    asm("fma.rn.f32x2 %0, %1, %2, %3;" : "=l"(d) : "l"(a), "l"(b), "l"(d));
}
__device__ __forceinline__ float fin(ull a) { float2 u = unpack2(a); return u.x + u.y; }

// ---------------- dtype sniff ----------------
__global__ void sniff_kernel(const int* __restrict__ ei32) {
    __shared__ int nonzero;
    if (threadIdx.x == 0) nonzero = 0;
    __syncthreads();
    for (int i = threadIdx.x; i < 1024; i += blockDim.x)
        if (ei32[2 * i + 1] != 0) atomicOr(&nonzero, 1);
    __syncthreads();
    if (threadIdx.x == 0) g_idx64 = (nonzero == 0) ? 1 : 0;
}

__global__ void zero_kernel(int n_nodes) {
    int idx = blockIdx.x * blockDim.x + threadIdx.x;
    int stride = gridDim.x * blockDim.x;
    for (int i = idx; i < n_nodes * 64; i += stride) g_agg[i] = 0.0f;
    for (int i = idx; i < n_nodes * 3; i += stride) g_aggc[i] = 0.0f;
    for (int i = idx; i < n_nodes; i += stride) g_cnt[i] = 0.0f;
}

// ---------------- transposed weight staging ----------------
// W: [K][64] row-major in gmem. Wt tile (j = k-pair, lane = col-pair):
// Wt[j*128 + l*4 + {0..3}] = { W[2j][2l], W[2j+1][2l], W[2j][2l+1], W[2j+1][2l+1] }
__device__ __forceinline__ void stage_wt(float* dst, const float* __restrict__ W,
                                         int elems, int tid, int nt) {
    for (int i = tid; i < elems; i += nt) {
        int j = i >> 7, rem = i & 127, l = rem >> 2, s = rem & 3;
        dst[i] = W[(2 * j + (s & 1)) * 64 + 2 * l + (s >> 1)];
    }
}

// ---------------- k-pair packed GEMM ----------------
// Xs: undup activations, row stride LDX (16B-aligned rows). Wt as above.
// Lane computes cols (2*lane, 2*lane+1); result = fin(acc) (even/odd-k halves).
template<int K4, int ROWS, int LDX>
__device__ __forceinline__ void gemmPK(const float* __restrict__ Xs,
                                       const float* __restrict__ Wt,
                                       int lane, ull bi0, ull bi1,
                                       ull acc0[ROWS], ull acc1[ROWS]) {
#pragma unroll
    for (int i = 0; i < ROWS; i++) { acc0[i] = bi0; acc1[i] = bi1; }
#pragma unroll 2
    for (int kc = 0; kc < K4; kc++) {
        const float* wp = Wt + kc * 256 + lane * 4;
        ulonglong2 wa = *(const ulonglong2*)(wp);        // j = 2kc
        ulonglong2 wb = *(const ulonglong2*)(wp + 128);  // j = 2kc+1
#pragma unroll
        for (int i = 0; i < ROWS; i++) {
            ulonglong2 xv = *(const ulonglong2*)(Xs + i * LDX + kc * 4);
            fma2(acc0[i], xv.x, wa.x);
            fma2(acc1[i], xv.x, wa.y);
            fma2(acc0[i], xv.y, wb.x);
            fma2(acc1[i], xv.y, wb.y);
        }
    }
}

// ---------------- per-node precompute ----------------
// smem: WAt 4096 | WBt 4096 | be1s 64 | Ht 8*512
__global__ void __launch_bounds__(256)
pre_kernel(const float* __restrict__ h, const float* __restrict__ We1,
           const float* __restrict__ be1, int N)
{
    extern __shared__ float sm[];
    float* WAt  = sm;
    float* WBt  = sm + 4096;
    float* be1s = sm + 8192;
    float* HtA  = sm + 8256;

    int tid = threadIdx.x;
    stage_wt(WAt, We1, 4096, tid, 256);
    stage_wt(WBt, We1 + 4096, 4096, tid, 256);
    if (tid < 64) be1s[tid] = be1[tid];
    __syncthreads();

    int w = tid >> 5, lane = tid & 31;
    float* Ht = HtA + w * 512;
    ull b0 = pack2(be1s[2 * lane], 0.0f);
    ull b1 = pack2(be1s[2 * lane + 1], 0.0f);
    ull z = pack2(0.0f, 0.0f);

    const int nGp = N / 8;   // 5000
    for (int g = blockIdx.x * 8 + w; g < nGp; g += gridDim.x * 8) {
        int base = g * 8;
        __syncwarp();
#pragma unroll
        for (int i = 0; i < 8; i++)
            *(float2*)&Ht[i * 64 + 2 * lane] = *(const float2*)&h[(base + i) * 64 + 2 * lane];
        __syncwarp();

        ull a0[8], a1[8];
        gemmPK<16, 8, 64>(Ht, WAt, lane, b0, b1, a0, a1);
#pragma unroll
        for (int i = 0; i < 8; i++)
            *(float2*)&g_pre[(base + i) * 128 + 2 * lane] = make_float2(fin(a0[i]), fin(a1[i]));
        gemmPK<16, 8, 64>(Ht, WBt, lane, z, z, a0, a1);
#pragma unroll
        for (int i = 0; i < 8; i++)
            *(float2*)&g_pre[(base + i) * 128 + 64 + 2 * lane] = make_float2(fin(a0[i]), fin(a1[i]));
    }
}

// ---------------- edge kernel ----------------
#define EROWS 8
// smem floats: We2t 4096 | Wc1t 4096 | w128s 64 | be2s 64 | bc1s 64 | wc2s 64
//              Md 8 warps * 8*64 = 4096 | meta 8 warps * 64 = 512  => 13056
__global__ void __launch_bounds__(256, 3)
edge_kernel4(const float* __restrict__ coord,
             const void* __restrict__ ei_raw, const float* __restrict__ emask,
             const float* __restrict__ We1, const float* __restrict__ We2,
             const float* __restrict__ be2, const float* __restrict__ Wc1,
             const float* __restrict__ bc1, const float* __restrict__ Wc2,
             int E, int N)
{
    extern __shared__ float sm[];
    float* We2t = sm;
    float* Wc1t = sm + 4096;
    float* w128s = sm + 8192;
    float* be2s = sm + 8256;
    float* bc1s = sm + 8320;
    float* wc2s = sm + 8384;
    float* MdA  = sm + 8448;
    float* metaA = sm + 12544;

    const long long* ei64 = (const long long*)ei_raw;
    const int*       ei32 = (const int*)ei_raw;
    const int is64 = g_idx64;

    int tid = threadIdx.x;
    stage_wt(We2t, We2, 4096, tid, 256);
    stage_wt(Wc1t, Wc1, 4096, tid, 256);
    if (tid < 64) {
        w128s[tid] = We1[128 * 64 + tid];
        be2s[tid] = be2[tid];
        bc1s[tid] = bc1[tid];
        wc2s[tid] = Wc2[tid];
    }
    __syncthreads();

    int w = tid >> 5, lane = tid & 31;
    float* Md   = MdA + w * 512;             // 8 rows x 64
    float* meta = metaA + w * 64;
    int*   sRow = (int*)meta;                // 8
    int*   sCol = (int*)(meta) + 8;          // 8
    float* sMk  = meta + 16;                 // 8
    float* sRad = meta + 24;                 // 8
    float* sCd  = meta + 32;                 // 24

    ull b20 = pack2(be2s[2 * lane], 0.0f);
    ull b21 = pack2(be2s[2 * lane + 1], 0.0f);
    ull bc0 = pack2(bc1s[2 * lane], 0.0f);
    ull bc1p = pack2(bc1s[2 * lane + 1], 0.0f);
    float2 w128p = *(float2*)&w128s[2 * lane];
    float2 wc2p  = *(float2*)&wc2s[2 * lane];

    const int nG = E / EROWS;   // 160000
    for (int g = blockIdx.x * 8 + w; g < nG; g += gridDim.x * 8) {
        int base = g * EROWS;
        __syncwarp();  // protect prev-iteration meta/Md reads

        // ---- meta (lanes 0..7, one edge each) ----
        if (lane < EROWS) {
            long long e = (long long)base + lane;
            int r, c;
            if (is64) { r = (int)ei64[e]; c = (int)ei64[(long long)E + e]; }
            else      { r = ei32[e];      c = ei32[(long long)E + e]; }
            r = min(max(r, 0), N - 1);
            c = min(max(c, 0), N - 1);
            sRow[lane] = r; sCol[lane] = c;
            float dx = coord[r * 3 + 0] - coord[c * 3 + 0];
            float dy = coord[r * 3 + 1] - coord[c * 3 + 1];
            float dz = coord[r * 3 + 2] - coord[c * 3 + 2];
            sCd[lane * 3 + 0] = dx; sCd[lane * 3 + 1] = dy; sCd[lane * 3 + 2] = dz;
            sRad[lane] = dx * dx + dy * dy + dz * dz;
            sMk[lane] = emask[e];
        }
        __syncwarp();

        // ---- combine precomputed layer-1 ----
#pragma unroll
        for (int i = 0; i < EROWS; i++) {
            int r = sRow[i], c = sCol[i];
            float2 pa = *(const float2*)&g_pre[r * 128 + 2 * lane];
            float2 pb = *(const float2*)&g_pre[c * 128 + 64 + 2 * lane];
            float rad = sRad[i];
            float m0 = silu(fmaf(rad, w128p.x, pa.x + pb.x));
            float m1 = silu(fmaf(rad, w128p.y, pa.y + pb.y));
            *(float2*)&Md[i * 64 + 2 * lane] = make_float2(m0, m1);
        }
        __syncwarp();

        // ---- layer 2: m = silu(m1 @ We2 + be2) * mask ----
        ull a0[EROWS], a1[EROWS];
        gemmPK<16, EROWS, 64>(Md, We2t, lane, b20, b21, a0, a1);
        __syncwarp();  // all Md reads done before overwrite
#pragma unroll
        for (int i = 0; i < EROWS; i++) {
            float mk = sMk[i];
            float mm0 = silu(fin(a0[i])) * mk;
            float mm1 = silu(fin(a1[i])) * mk;
            *(float2*)&Md[i * 64 + 2 * lane] = make_float2(mm0, mm1);
            asm volatile("red.global.add.v2.f32 [%0], {%1, %2};"
                         :: "l"(g_agg + sRow[i] * 64 + 2 * lane), "f"(mm0), "f"(mm1)
                         : "memory");
        }
        __syncwarp();

        // ---- coord MLP: cp = silu(m @ Wc1 + bc1) . Wc2 ----
        gemmPK<16, EROWS, 64>(Md, Wc1t, lane, bc0, bc1p, a0, a1);
#pragma unroll
        for (int i = 0; i < EROWS; i++) {
            float s = silu(fin(a0[i])) * wc2p.x + silu(fin(a1[i])) * wc2p.y;
#pragma unroll
            for (int m = 16; m > 0; m >>= 1)
                s += __shfl_xor_sync(0xffffffffu, s, m);
            int r = sRow[i];
            if (lane < 3) {
                atomicAdd(&g_aggc[r * 3 + lane], sCd[i * 3 + lane] * s * sMk[i]);
            } else if (lane == 3) {
                atomicAdd(&g_cnt[r], 1.0f);
            }
        }
    }
}

// ---------------- node kernel ----------------
// smem floats: W1t 8192 | W2t 4096 | b1s 64 | b2s 64 | Nin 8*1024 | Hb 8*512
__global__ void __launch_bounds__(256)
node_kernel(const float* __restrict__ h, const float* __restrict__ coord,
            const float* __restrict__ Wn1, const float* __restrict__ bn1,
            const float* __restrict__ Wn2, const float* __restrict__ bn2,
            float* __restrict__ out, int N, long long out_size)
{
    extern __shared__ float sm[];
    float* W1t = sm;                // 8192 (K=128)
    float* W2t = sm + 8192;         // 4096
    float* b1s = sm + 12288;
    float* b2s = sm + 12352;
    float* NinA = sm + 12416;       // 8*1024
    float* HbA  = sm + 20608;       // 8*512

    int tid = threadIdx.x;
    stage_wt(W1t, Wn1, 8192, tid, 256);
    stage_wt(W2t, Wn2, 4096, tid, 256);
    if (tid < 64) { b1s[tid] = bn1[tid]; b2s[tid] = bn2[tid]; }
    __syncthreads();

    int w = tid >> 5, lane = tid & 31;
    float* Nin = NinA + w * 1024;   // 8 rows x 128
    float* Hb  = HbA + w * 512;     // 8 rows x 64
    ull b10 = pack2(b1s[2 * lane], 0.0f);
    ull b11 = pack2(b1s[2 * lane + 1], 0.0f);
    ull b20 = pack2(b2s[2 * lane], 0.0f);
    ull b21 = pack2(b2s[2 * lane + 1], 0.0f);

    float* hout = out;
    float* cout = out + (long long)N * 64;
    const bool has_coord_out = out_size >= (long long)N * 67;

    const int nGp = N / 8;   // 5000
    for (int g = blockIdx.x * 8 + w; g < nGp; g += gridDim.x * 8) {
        int base = g * 8;
        __syncwarp();
#pragma unroll
        for (int i = 0; i < 8; i++) {
            int n = base + i;
            *(float2*)&Nin[i * 128 + 2 * lane]      = *(const float2*)&h[(long long)n * 64 + 2 * lane];
            *(float2*)&Nin[i * 128 + 64 + 2 * lane] = *(const float2*)&g_agg[(long long)n * 64 + 2 * lane];
            if (lane < 3 && has_coord_out) {
                float cnt = fmaxf(g_cnt[n], 1.0f);
                cout[n * 3 + lane] = coord[n * 3 + lane] + g_aggc[n * 3 + lane] / cnt;
            }
        }
        __syncwarp();

        ull a0[8], a1[8];
        gemmPK<32, 8, 128>(Nin, W1t, lane, b10, b11, a0, a1);
        __syncwarp();
#pragma unroll
        for (int i = 0; i < 8; i++)
            *(float2*)&Hb[i * 64 + 2 * lane] = make_float2(silu(fin(a0[i])), silu(fin(a1[i])));
        __syncwarp();

        gemmPK<16, 8, 64>(Hb, W2t, lane, b20, b21, a0, a1);
#pragma unroll
        for (int i = 0; i < 8; i++) {
            int n = base + i;
            *(float2*)&hout[(long long)n * 64 + 2 * lane] = make_float2(fin(a0[i]), fin(a1[i]));
        }
    }
}

extern "C" void kernel_launch(void* const* d_in, const int* in_sizes, int n_in,
                              void* d_out, int out_size) {
    const float* h     = (const float*)d_in[0];
    const float* coord = (const float*)d_in[1];
    const void*  ei    = d_in[2];
    const float* emask = (const float*)d_in[3];
    const float* We1   = (const float*)d_in[4];
    const float* be1   = (const float*)d_in[5];
    const float* We2   = (const float*)d_in[6];
    const float* be2   = (const float*)d_in[7];
    const float* Wn1   = (const float*)d_in[8];
    const float* bn1   = (const float*)d_in[9];
    const float* Wn2   = (const float*)d_in[10];
    const float* bn2   = (const float*)d_in[11];
    const float* Wc1   = (const float*)d_in[12];
    const float* bc1   = (const float*)d_in[13];
    const float* Wc2   = (const float*)d_in[14];
    float* out = (float*)d_out;

    int N = in_sizes[0] / 64;   // 40000
    int E = in_sizes[3];        // 1280000

    size_t shP = (size_t)(4096 + 4096 + 64 + 8 * 512) * sizeof(float);
    size_t shE = (size_t)13056 * sizeof(float);
    size_t shN = (size_t)(8192 + 4096 + 64 + 64 + 8 * 1024 + 8 * 512) * sizeof(float);

    cudaFuncSetAttribute(pre_kernel,   cudaFuncAttributeMaxDynamicSharedMemorySize, (int)shP);
    cudaFuncSetAttribute(edge_kernel4, cudaFuncAttributeMaxDynamicSharedMemorySize, (int)shE);
    cudaFuncSetAttribute(node_kernel,  cudaFuncAttributeMaxDynamicSharedMemorySize, (int)shN);

    sniff_kernel<<<1, 256>>>((const int*)ei);
    zero_kernel<<<512, 256>>>(N);
    pre_kernel<<<296, 256, shP>>>(h, We1, be1, N);
    edge_kernel4<<<444, 256, shE>>>(coord, ei, emask,
                                    We1, We2, be2, Wc1, bc1, Wc2, E, N);
    node_kernel<<<296, 256, shN>>>(h, coord, Wn1, bn1, Wn2, bn2, out, N,
                                   (long long)out_size);
}

// round 8
// speedup vs baseline: 4.4179x; 1.9405x over previous
#include <cuda_runtime.h>

// Problem constants: N=40000, F=64, H=64, E=1280000
#define MAXN 40000

__device__ float g_pre[MAXN * 128]; // [P_A = h@We1_top + be1 | P_B = h@We1_bot]
__device__ float g_agg[MAXN * 64];  // sum of m per row-node
__device__ float g_aggc[MAXN * 3];  // sum of trans per row-node
__device__ float g_cnt[MAXN];       // edge count per row-node
__device__ int   g_idx64;           // edge_index dtype flag

typedef unsigned long long ull;
typedef unsigned int uint;

__device__ __forceinline__ float silu(float x) {
    return __fdividef(x, 1.0f + __expf(-x));
}
__device__ __forceinline__ ull pack2(float lo, float hi) {
    ull r; asm("mov.b64 %0, {%1, %2};" : "=l"(r) : "f"(lo), "f"(hi)); return r;
}
__device__ __forceinline__ float2 unpack2(ull v) {
    float2 f; asm("mov.b64 {%0, %1}, %2;" : "=f"(f.x), "=f"(f.y) : "l"(v)); return f;
}
__device__ __forceinline__ void fma2(ull& d, ull a, ull b) {
    asm("fma.rn.f32x2 %0, %1, %2, %3;" : "=l"(d) : "l"(a), "l"(b), "l"(d));
}
__device__ __forceinline__ float fin(ull a) { float2 u = unpack2(a); return u.x + u.y; }

__device__ __forceinline__ uint f2tf(float x) {
    uint r; asm("cvt.rna.tf32.f32 %0, %1;" : "=r"(r) : "f"(x)); return r;
}
__device__ __forceinline__ void mma_tf32(float d[4], const uint a[4], const uint b[2]) {
    asm("mma.sync.aligned.m16n8k8.row.col.f32.tf32.tf32.f32 "
        "{%0,%1,%2,%3}, {%4,%5,%6,%7}, {%8,%9}, {%0,%1,%2,%3};"
        : "+f"(d[0]), "+f"(d[1]), "+f"(d[2]), "+f"(d[3])
        : "r"(a[0]), "r"(a[1]), "r"(a[2]), "r"(a[3]), "r"(b[0]), "r"(b[1]));
}

// ---------------- dtype sniff ----------------
__global__ void sniff_kernel(const int* __restrict__ ei32) {
    __shared__ int nonzero;
    if (threadIdx.x == 0) nonzero = 0;
    __syncthreads();
    for (int i = threadIdx.x; i < 1024; i += blockDim.x)
        if (ei32[2 * i + 1] != 0) atomicOr(&nonzero, 1);
    __syncthreads();
    if (threadIdx.x == 0) g_idx64 = (nonzero == 0) ? 1 : 0;
}

__global__ void zero_kernel(int n_nodes) {
    int idx = blockIdx.x * blockDim.x + threadIdx.x;
    int stride = gridDim.x * blockDim.x;
    for (int i = idx; i < n_nodes * 64; i += stride) g_agg[i] = 0.0f;
    for (int i = idx; i < n_nodes * 3; i += stride) g_aggc[i] = 0.0f;
    for (int i = idx; i < n_nodes; i += stride) g_cnt[i] = 0.0f;
}

// ---------------- transposed weight staging (scalar path, pre/node) ----------------
// W: [K][64] row-major. Wt[j*128 + l*4 + {0..3}] = {W[2j][2l],W[2j+1][2l],W[2j][2l+1],W[2j+1][2l+1]}
__device__ __forceinline__ void stage_wt(float* dst, const float* __restrict__ W,
                                         int elems, int tid, int nt) {
    for (int i = tid; i < elems; i += nt) {
        int j = i >> 7, rem = i & 127, l = rem >> 2, s = rem & 3;
        dst[i] = W[(2 * j + (s & 1)) * 64 + 2 * l + (s >> 1)];
    }
}

// ---------------- k-pair packed scalar GEMM (pre/node kernels) ----------------
template<int K4, int ROWS, int LDX>
__device__ __forceinline__ void gemmPK(const float* __restrict__ Xs,
                                       const float* __restrict__ Wt,
                                       int lane, ull bi0, ull bi1,
                                       ull acc0[ROWS], ull acc1[ROWS]) {
#pragma unroll
    for (int i = 0; i < ROWS; i++) { acc0[i] = bi0; acc1[i] = bi1; }
#pragma unroll 2
    for (int kc = 0; kc < K4; kc++) {
        const float* wp = Wt + kc * 256 + lane * 4;
        ulonglong2 wa = *(const ulonglong2*)(wp);
        ulonglong2 wb = *(const ulonglong2*)(wp + 128);
#pragma unroll
        for (int i = 0; i < ROWS; i++) {
            ulonglong2 xv = *(const ulonglong2*)(Xs + i * LDX + kc * 4);
            fma2(acc0[i], xv.x, wa.x);
            fma2(acc1[i], xv.x, wa.y);
            fma2(acc0[i], xv.y, wb.x);
            fma2(acc1[i], xv.y, wb.y);
        }
    }
}

// ---------------- per-node precompute ----------------
__global__ void __launch_bounds__(256)
pre_kernel(const float* __restrict__ h, const float* __restrict__ We1,
           const float* __restrict__ be1, int N)
{
    extern __shared__ float sm[];
    float* WAt  = sm;
    float* WBt  = sm + 4096;
    float* be1s = sm + 8192;
    float* HtA  = sm + 8256;

    int tid = threadIdx.x;
    stage_wt(WAt, We1, 4096, tid, 256);
    stage_wt(WBt, We1 + 4096, 4096, tid, 256);
    if (tid < 64) be1s[tid] = be1[tid];
    __syncthreads();

    int w = tid >> 5, lane = tid & 31;
    float* Ht = HtA + w * 512;
    ull b0 = pack2(be1s[2 * lane], 0.0f);
    ull b1 = pack2(be1s[2 * lane + 1], 0.0f);
    ull z = pack2(0.0f, 0.0f);

    const int nGp = N / 8;
    for (int g = blockIdx.x * 8 + w; g < nGp; g += gridDim.x * 8) {
        int base = g * 8;
        __syncwarp();
#pragma unroll
        for (int i = 0; i < 8; i++)
            *(float2*)&Ht[i * 64 + 2 * lane] = *(const float2*)&h[(base + i) * 64 + 2 * lane];
        __syncwarp();

        ull a0[8], a1[8];
        gemmPK<16, 8, 64>(Ht, WAt, lane, b0, b1, a0, a1);
#pragma unroll
        for (int i = 0; i < 8; i++)
            *(float2*)&g_pre[(base + i) * 128 + 2 * lane] = make_float2(fin(a0[i]), fin(a1[i]));
        gemmPK<16, 8, 64>(Ht, WBt, lane, z, z, a0, a1);
#pragma unroll
        for (int i = 0; i < 8; i++)
            *(float2*)&g_pre[(base + i) * 128 + 64 + 2 * lane] = make_float2(fin(a0[i]), fin(a1[i]));
    }
}

// ---------------- edge kernel: mma.sync tf32 ----------------
// Each warp owns a 16-edge slice: combine -> GEMM1(We2) -> GEMM2(Wc1), warp-autonomous.
// smem floats:
//   We2t 64*72=4608 @0 | Wc1t 4608 @4608 | w128s 64 @9216 | be2s 64 @9280
//   bc1s 64 @9344 | wc2s 64 @9408 | m1 slices 8*16*68=8704 @9472 | meta 8*128 @18176
// total 19200 floats = 76800 B
#define SME_M1   9472
#define SME_META 18176
#define SME_TOT  19200

// warp GEMM: A = Ms[16][68] (tf32 bits), B = Wt[64][72] (tf32 bits), bias[64] fp32.
__device__ __forceinline__ void gemm_mma(const float* __restrict__ Ms,
                                         const float* __restrict__ Wt,
                                         const float* __restrict__ bias,
                                         int lane, float acc[8][4]) {
    int qr = lane >> 2, qk = lane & 3;
#pragma unroll
    for (int nt = 0; nt < 8; nt++) {
        float2 b = *(const float2*)&bias[nt * 8 + 2 * qk];
        acc[nt][0] = b.x; acc[nt][1] = b.y; acc[nt][2] = b.x; acc[nt][3] = b.y;
    }
#pragma unroll
    for (int kt = 0; kt < 8; kt++) {
        uint a[4];
        const float* ap = Ms + kt * 8 + qk;
        a[0] = __float_as_uint(ap[qr * 68]);
        a[1] = __float_as_uint(ap[(qr + 8) * 68]);
        a[2] = __float_as_uint(ap[qr * 68 + 4]);
        a[3] = __float_as_uint(ap[(qr + 8) * 68 + 4]);
        const float* bp = Wt + (kt * 8 + qk) * 72 + qr;
#pragma unroll
        for (int nt = 0; nt < 8; nt++) {
            uint b[2];
            b[0] = __float_as_uint(bp[nt * 8]);
            b[1] = __float_as_uint(bp[nt * 8 + 4 * 72]);
            mma_tf32(acc[nt], a, b);
        }
    }
}

__global__ void __launch_bounds__(256, 2)
edge_kernel5(const float* __restrict__ coord,
             const void* __restrict__ ei_raw, const float* __restrict__ emask,
             const float* __restrict__ We1, const float* __restrict__ We2,
             const float* __restrict__ be2, const float* __restrict__ Wc1,
             const float* __restrict__ bc1, const float* __restrict__ Wc2,
             int E, int N)
{
    extern __shared__ float sm[];
    float* We2t = sm;            // [64][72] tf32 bits
    float* Wc1t = sm + 4608;     // [64][72] tf32 bits
    float* w128s = sm + 9216;
    float* be2s = sm + 9280;
    float* bc1s = sm + 9344;
    float* wc2s = sm + 9408;

    const long long* ei64 = (const long long*)ei_raw;
    const int*       ei32 = (const int*)ei_raw;
    const int is64 = g_idx64;

    int tid = threadIdx.x;
    // stage weights as tf32 (row-major k x n, padded stride 72)
    for (int i = tid; i < 4096; i += 256) {
        int k = i >> 6, n = i & 63;
        We2t[k * 72 + n] = __uint_as_float(f2tf(We2[i]));
        Wc1t[k * 72 + n] = __uint_as_float(f2tf(Wc1[i]));
    }
    if (tid < 64) {
        w128s[tid] = We1[128 * 64 + tid];
        be2s[tid] = be2[tid];
        bc1s[tid] = bc1[tid];
        wc2s[tid] = Wc2[tid];
    }
    __syncthreads();

    int w = tid >> 5, lane = tid & 31;
    float* Ms   = sm + SME_M1 + w * 1088;     // 16 rows x 68
    float* meta = sm + SME_META + w * 128;
    int*   sRow = (int*)meta;                 // 16
    int*   sCol = (int*)meta + 16;            // 16
    float* sMk  = meta + 32;                  // 16
    float* sRad = meta + 48;                  // 16
    float* sCd  = meta + 64;                  // 48

    int qr = lane >> 2, qk = lane & 3;
    float2 w128p = *(float2*)&w128s[2 * lane];

    const int nG = E / 16;   // 80000
    for (int g = blockIdx.x * 8 + w; g < nG; g += gridDim.x * 8) {
        int base = g * 16;
        __syncwarp();  // protect prev-iteration smem reads

        // ---- meta (lanes 0..15, one edge each) ----
        if (lane < 16) {
            long long e = (long long)base + lane;
            int r, c;
            if (is64) { r = (int)ei64[e]; c = (int)ei64[(long long)E + e]; }
            else      { r = ei32[e];      c = ei32[(long long)E + e]; }
            r = min(max(r, 0), N - 1);
            c = min(max(c, 0), N - 1);
            sRow[lane] = r; sCol[lane] = c;
            float dx = coord[r * 3 + 0] - coord[c * 3 + 0];
            float dy = coord[r * 3 + 1] - coord[c * 3 + 1];
            float dz = coord[r * 3 + 2] - coord[c * 3 + 2];
            sCd[lane * 3 + 0] = dx; sCd[lane * 3 + 1] = dy; sCd[lane * 3 + 2] = dz;
            sRad[lane] = dx * dx + dy * dy + dz * dz;
            sMk[lane] = emask[e];
        }
        __syncwarp();

        // ---- combine precomputed layer-1, store tf32 into Ms ----
#pragma unroll 4
        for (int i = 0; i < 16; i++) {
            int r = sRow[i], c = sCol[i];
            float2 pa = *(const float2*)&g_pre[r * 128 + 2 * lane];
            float2 pb = *(const float2*)&g_pre[c * 128 + 64 + 2 * lane];
            float rad = sRad[i];
            float m0 = silu(fmaf(rad, w128p.x, pa.x + pb.x));
            float m1 = silu(fmaf(rad, w128p.y, pa.y + pb.y));
            uint2 t = make_uint2(f2tf(m0), f2tf(m1));
            *(uint2*)&Ms[i * 68 + 2 * lane] = t;
        }
        __syncwarp();

        // ---- layer 2: m = silu(m1 @ We2 + be2) * mask ----
        float acc[8][4];
        gemm_mma(Ms, We2t, be2s, lane, acc);
        __syncwarp();  // all A-frag reads done before overwrite

        float mk0 = sMk[qr], mk1 = sMk[qr + 8];
        int r0 = sRow[qr], r1 = sRow[qr + 8];
#pragma unroll
        for (int nt = 0; nt < 8; nt++) {
            int colb = nt * 8 + 2 * qk;
            float m00 = silu(acc[nt][0]) * mk0;
            float m01 = silu(acc[nt][1]) * mk0;
            float m10 = silu(acc[nt][2]) * mk1;
            float m11 = silu(acc[nt][3]) * mk1;
            asm volatile("red.global.add.v2.f32 [%0], {%1, %2};"
                         :: "l"(g_agg + r0 * 64 + colb), "f"(m00), "f"(m01) : "memory");
            asm volatile("red.global.add.v2.f32 [%0], {%1, %2};"
                         :: "l"(g_agg + r1 * 64 + colb), "f"(m10), "f"(m11) : "memory");
            *(uint2*)&Ms[qr * 68 + colb] = make_uint2(f2tf(m00), f2tf(m01));
            *(uint2*)&Ms[(qr + 8) * 68 + colb] = make_uint2(f2tf(m10), f2tf(m11));
        }
        __syncwarp();

        // ---- coord MLP: cp = silu(m @ Wc1 + bc1) . Wc2 ----
        gemm_mma(Ms, Wc1t, bc1s, lane, acc);

        float ps0 = 0.0f, ps1 = 0.0f;
#pragma unroll
        for (int nt = 0; nt < 8; nt++) {
            float2 wc = *(const float2*)&wc2s[nt * 8 + 2 * qk];
            ps0 += silu(acc[nt][0]) * wc.x + silu(acc[nt][1]) * wc.y;
            ps1 += silu(acc[nt][2]) * wc.x + silu(acc[nt][3]) * wc.y;
        }
        ps0 += __shfl_xor_sync(0xffffffffu, ps0, 1);
        ps0 += __shfl_xor_sync(0xffffffffu, ps0, 2);
        ps1 += __shfl_xor_sync(0xffffffffu, ps1, 1);
        ps1 += __shfl_xor_sync(0xffffffffu, ps1, 2);

        if (qk < 3) {
            atomicAdd(&g_aggc[r0 * 3 + qk], sCd[qr * 3 + qk] * ps0 * mk0);
            atomicAdd(&g_aggc[r1 * 3 + qk], sCd[(qr + 8) * 3 + qk] * ps1 * mk1);
        } else {
            atomicAdd(&g_cnt[r0], 1.0f);
            atomicAdd(&g_cnt[r1], 1.0f);
        }
    }
}

// ---------------- node kernel (fp32 exact, unchanged) ----------------
__global__ void __launch_bounds__(256)
node_kernel(const float* __restrict__ h, const float* __restrict__ coord,
            const float* __restrict__ Wn1, const float* __restrict__ bn1,
            const float* __restrict__ Wn2, const float* __restrict__ bn2,
            float* __restrict__ out, int N, long long out_size)
{
    extern __shared__ float sm[];
    float* W1t = sm;
    float* W2t = sm + 8192;
    float* b1s = sm + 12288;
    float* b2s = sm + 12352;
    float* NinA = sm + 12416;
    float* HbA  = sm + 20608;

    int tid = threadIdx.x;
    stage_wt(W1t, Wn1, 8192, tid, 256);
    stage_wt(W2t, Wn2, 4096, tid, 256);
    if (tid < 64) { b1s[tid] = bn1[tid]; b2s[tid] = bn2[tid]; }
    __syncthreads();

    int w = tid >> 5, lane = tid & 31;
    float* Nin = NinA + w * 1024;
    float* Hb  = HbA + w * 512;
    ull b10 = pack2(b1s[2 * lane], 0.0f);
    ull b11 = pack2(b1s[2 * lane + 1], 0.0f);
    ull b20 = pack2(b2s[2 * lane], 0.0f);
    ull b21 = pack2(b2s[2 * lane + 1], 0.0f);

    float* hout = out;
    float* cout = out + (long long)N * 64;
    const bool has_coord_out = out_size >= (long long)N * 67;

    const int nGp = N / 8;
    for (int g = blockIdx.x * 8 + w; g < nGp; g += gridDim.x * 8) {
        int base = g * 8;
        __syncwarp();
#pragma unroll
        for (int i = 0; i < 8; i++) {
            int n = base + i;
            *(float2*)&Nin[i * 128 + 2 * lane]      = *(const float2*)&h[(long long)n * 64 + 2 * lane];
            *(float2*)&Nin[i * 128 + 64 + 2 * lane] = *(const float2*)&g_agg[(long long)n * 64 + 2 * lane];
            if (lane < 3 && has_coord_out) {
                float cnt = fmaxf(g_cnt[n], 1.0f);
                cout[n * 3 + lane] = coord[n * 3 + lane] + g_aggc[n * 3 + lane] / cnt;
            }
        }
        __syncwarp();

        ull a0[8], a1[8];
        gemmPK<32, 8, 128>(Nin, W1t, lane, b10, b11, a0, a1);
        __syncwarp();
#pragma unroll
        for (int i = 0; i < 8; i++)
            *(float2*)&Hb[i * 64 + 2 * lane] = make_float2(silu(fin(a0[i])), silu(fin(a1[i])));
        __syncwarp();

        gemmPK<16, 8, 64>(Hb, W2t, lane, b20, b21, a0, a1);
#pragma unroll
        for (int i = 0; i < 8; i++) {
            int n = base + i;
            *(float2*)&hout[(long long)n * 64 + 2 * lane] = make_float2(fin(a0[i]), fin(a1[i]));
        }
    }
}

extern "C" void kernel_launch(void* const* d_in, const int* in_sizes, int n_in,
                              void* d_out, int out_size) {
    const float* h     = (const float*)d_in[0];
    const float* coord = (const float*)d_in[1];
    const void*  ei    = d_in[2];
    const float* emask = (const float*)d_in[3];
    const float* We1   = (const float*)d_in[4];
    const float* be1   = (const float*)d_in[5];
    const float* We2   = (const float*)d_in[6];
    const float* be2   = (const float*)d_in[7];
    const float* Wn1   = (const float*)d_in[8];
    const float* bn1   = (const float*)d_in[9];
    const float* Wn2   = (const float*)d_in[10];
    const float* bn2   = (const float*)d_in[11];
    const float* Wc1   = (const float*)d_in[12];
    const float* bc1   = (const float*)d_in[13];
    const float* Wc2   = (const float*)d_in[14];
    float* out = (float*)d_out;

    int N = in_sizes[0] / 64;   // 40000
    int E = in_sizes[3];        // 1280000

    size_t shP = (size_t)(4096 + 4096 + 64 + 8 * 512) * sizeof(float);
    size_t shE = (size_t)SME_TOT * sizeof(float);
    size_t shN = (size_t)(8192 + 4096 + 64 + 64 + 8 * 1024 + 8 * 512) * sizeof(float);

    cudaFuncSetAttribute(pre_kernel,   cudaFuncAttributeMaxDynamicSharedMemorySize, (int)shP);
    cudaFuncSetAttribute(edge_kernel5, cudaFuncAttributeMaxDynamicSharedMemorySize, (int)shE);
    cudaFuncSetAttribute(node_kernel,  cudaFuncAttributeMaxDynamicSharedMemorySize, (int)shN);

    sniff_kernel<<<1, 256>>>((const int*)ei);
    zero_kernel<<<512, 256>>>(N);
    pre_kernel<<<296, 256, shP>>>(h, We1, be1, N);
    edge_kernel5<<<296, 256, shE>>>(coord, ei, emask,
                                    We1, We2, be2, Wc1, bc1, Wc2, E, N);
    node_kernel<<<296, 256, shN>>>(h, coord, Wn1, bn1, Wn2, bn2, out, N,
                                   (long long)out_size);
}

// round 9
// speedup vs baseline: 4.7428x; 1.0735x over previous
#include <cuda_runtime.h>

// Problem constants: N=40000, F=64, H=64, E=1280000
#define MAXN 40000

__device__ float g_pre[MAXN * 128]; // [P_A = h@We1_top + be1 | P_B = h@We1_bot]
__device__ float g_agg[MAXN * 64];  // sum of m per row-node
__device__ float g_aggc[MAXN * 3];  // sum of trans per row-node
__device__ float g_cnt[MAXN];       // edge count per row-node
__device__ int   g_idx64;           // edge_index dtype flag

typedef unsigned long long ull;
typedef unsigned int uint;

__device__ __forceinline__ float silu(float x) {
    return __fdividef(x, 1.0f + __expf(-x));
}
// 1-MUFU silu: x/2 * (1 + tanh(x/2))
__device__ __forceinline__ float silu_t(float x) {
    float t;
    asm("tanh.approx.f32 %0, %1;" : "=f"(t) : "f"(x * 0.5f));
    return fmaf(0.5f * x, t, 0.5f * x);
}
__device__ __forceinline__ ull pack2(float lo, float hi) {
    ull r; asm("mov.b64 %0, {%1, %2};" : "=l"(r) : "f"(lo), "f"(hi)); return r;
}
__device__ __forceinline__ float2 unpack2(ull v) {
    float2 f; asm("mov.b64 {%0, %1}, %2;" : "=f"(f.x), "=f"(f.y) : "l"(v)); return f;
}
__device__ __forceinline__ void fma2(ull& d, ull a, ull b) {
    asm("fma.rn.f32x2 %0, %1, %2, %3;" : "=l"(d) : "l"(a), "l"(b), "l"(d));
}
__device__ __forceinline__ float fin(ull a) { float2 u = unpack2(a); return u.x + u.y; }

__device__ __forceinline__ uint f2tf(float x) {
    uint r; asm("cvt.rna.tf32.f32 %0, %1;" : "=r"(r) : "f"(x)); return r;
}
__device__ __forceinline__ void mma_tf32(float d[4], const uint a[4], const uint b[2]) {
    asm("mma.sync.aligned.m16n8k8.row.col.f32.tf32.tf32.f32 "
        "{%0,%1,%2,%3}, {%4,%5,%6,%7}, {%8,%9}, {%0,%1,%2,%3};"
        : "+f"(d[0]), "+f"(d[1]), "+f"(d[2]), "+f"(d[3])
        : "r"(a[0]), "r"(a[1]), "r"(a[2]), "r"(a[3]), "r"(b[0]), "r"(b[1]));
}

// ---------------- dtype sniff ----------------
__global__ void sniff_kernel(const int* __restrict__ ei32) {
    __shared__ int nonzero;
    if (threadIdx.x == 0) nonzero = 0;
    __syncthreads();
    for (int i = threadIdx.x; i < 1024; i += blockDim.x)
        if (ei32[2 * i + 1] != 0) atomicOr(&nonzero, 1);
    __syncthreads();
    if (threadIdx.x == 0) g_idx64 = (nonzero == 0) ? 1 : 0;
}

__global__ void zero_kernel(int n_nodes) {
    int idx = blockIdx.x * blockDim.x + threadIdx.x;
    int stride = gridDim.x * blockDim.x;
    for (int i = idx; i < n_nodes * 64; i += stride) g_agg[i] = 0.0f;
    for (int i = idx; i < n_nodes * 3; i += stride) g_aggc[i] = 0.0f;
    for (int i = idx; i < n_nodes; i += stride) g_cnt[i] = 0.0f;
}

// ---------------- transposed weight staging (scalar path) ----------------
__device__ __forceinline__ void stage_wt(float* dst, const float* __restrict__ W,
                                         int elems, int tid, int nt) {
    for (int i = tid; i < elems; i += nt) {
        int j = i >> 7, rem = i & 127, l = rem >> 2, s = rem & 3;
        dst[i] = W[(2 * j + (s & 1)) * 64 + 2 * l + (s >> 1)];
    }
}

// ---------------- k-pair packed scalar GEMM (pre/node kernels) ----------------
template<int K4, int ROWS, int LDX>
__device__ __forceinline__ void gemmPK(const float* __restrict__ Xs,
                                       const float* __restrict__ Wt,
                                       int lane, ull bi0, ull bi1,
                                       ull acc0[ROWS], ull acc1[ROWS]) {
#pragma unroll
    for (int i = 0; i < ROWS; i++) { acc0[i] = bi0; acc1[i] = bi1; }
#pragma unroll 2
    for (int kc = 0; kc < K4; kc++) {
        const float* wp = Wt + kc * 256 + lane * 4;
        ulonglong2 wa = *(const ulonglong2*)(wp);
        ulonglong2 wb = *(const ulonglong2*)(wp + 128);
#pragma unroll
        for (int i = 0; i < ROWS; i++) {
            ulonglong2 xv = *(const ulonglong2*)(Xs + i * LDX + kc * 4);
            fma2(acc0[i], xv.x, wa.x);
            fma2(acc1[i], xv.x, wa.y);
            fma2(acc0[i], xv.y, wb.x);
            fma2(acc1[i], xv.y, wb.y);
        }
    }
}

// ---------------- per-node precompute ----------------
__global__ void __launch_bounds__(256)
pre_kernel(const float* __restrict__ h, const float* __restrict__ We1,
           const float* __restrict__ be1, int N)
{
    extern __shared__ float sm[];
    float* WAt  = sm;
    float* WBt  = sm + 4096;
    float* be1s = sm + 8192;
    float* HtA  = sm + 8256;

    int tid = threadIdx.x;
    stage_wt(WAt, We1, 4096, tid, 256);
    stage_wt(WBt, We1 + 4096, 4096, tid, 256);
    if (tid < 64) be1s[tid] = be1[tid];
    __syncthreads();

    int w = tid >> 5, lane = tid & 31;
    float* Ht = HtA + w * 512;
    ull b0 = pack2(be1s[2 * lane], 0.0f);
    ull b1 = pack2(be1s[2 * lane + 1], 0.0f);
    ull z = pack2(0.0f, 0.0f);

    const int nGp = N / 8;
    for (int g = blockIdx.x * 8 + w; g < nGp; g += gridDim.x * 8) {
        int base = g * 8;
        __syncwarp();
#pragma unroll
        for (int i = 0; i < 8; i++)
            *(float2*)&Ht[i * 64 + 2 * lane] = *(const float2*)&h[(base + i) * 64 + 2 * lane];
        __syncwarp();

        ull a0[8], a1[8];
        gemmPK<16, 8, 64>(Ht, WAt, lane, b0, b1, a0, a1);
#pragma unroll
        for (int i = 0; i < 8; i++)
            *(float2*)&g_pre[(base + i) * 128 + 2 * lane] = make_float2(fin(a0[i]), fin(a1[i]));
        gemmPK<16, 8, 64>(Ht, WBt, lane, z, z, a0, a1);
#pragma unroll
        for (int i = 0; i < 8; i++)
            *(float2*)&g_pre[(base + i) * 128 + 64 + 2 * lane] = make_float2(fin(a0[i]), fin(a1[i]));
    }
}

// ---------------- edge kernel: mma.sync tf32, M=32 warp tile ----------------
// smem floats:
//   We2t [64][72]=4608 @0 | Wc1t 4608 @4608 | w128s 64 @9216 | be2s 64 @9280
//   bc1s 64 @9344 | wc2s 64 @9408 | Ms 8*32*64=16384 @9472 | meta 8*256 @25856
// total 27904 floats = 111616 B  (2 blocks/SM = 223 KB <= 228)
#define SME_MS   9472
#define SME_META 25856
#define SME_TOT  27904

// Ms swizzle: addr(row, col) = row*64 + (col ^ ((row&7)<<2))

// M=32 warp GEMM: rows {qr, qr+8} (tile0) and {qr+16, qr+24} (tile1).
__device__ __forceinline__ void gemm_mma32(const float* __restrict__ Ms,
                                           const float* __restrict__ Wt,
                                           const float* __restrict__ bias,
                                           int qr, int qk, float acc[2][8][4]) {
#pragma unroll
    for (int nt = 0; nt < 8; nt++) {
        float2 b = *(const float2*)&bias[nt * 8 + 2 * qk];
#pragma unroll
        for (int mt = 0; mt < 2; mt++) {
            acc[mt][nt][0] = b.x; acc[mt][nt][1] = b.y;
            acc[mt][nt][2] = b.x; acc[mt][nt][3] = b.y;
        }
    }
    const int sw = qr << 2;
#pragma unroll
    for (int kt = 0; kt < 8; kt++) {
        int c0 = (kt * 8 + qk) ^ sw;
        int c1 = (kt * 8 + qk + 4) ^ sw;
        const float* r0 = Ms + qr * 64;
        uint a0[4], a1[4];
        a0[0] = __float_as_uint(r0[c0]);
        a0[1] = __float_as_uint(r0[512 + c0]);    // qr+8
        a0[2] = __float_as_uint(r0[c1]);
        a0[3] = __float_as_uint(r0[512 + c1]);
        a1[0] = __float_as_uint(r0[1024 + c0]);   // qr+16
        a1[1] = __float_as_uint(r0[1536 + c0]);   // qr+24
        a1[2] = __float_as_uint(r0[1024 + c1]);
        a1[3] = __float_as_uint(r0[1536 + c1]);
        const float* bp = Wt + (kt * 8 + qk) * 72 + qr;
#pragma unroll
        for (int nt = 0; nt < 8; nt++) {
            uint b[2];
            b[0] = __float_as_uint(bp[nt * 8]);
            b[1] = __float_as_uint(bp[nt * 8 + 4 * 72]);
            mma_tf32(acc[0][nt], a0, b);
            mma_tf32(acc[1][nt], a1, b);
        }
    }
}

__global__ void __launch_bounds__(256, 2)
edge_kernel6(const float* __restrict__ coord,
             const void* __restrict__ ei_raw, const float* __restrict__ emask,
             const float* __restrict__ We1, const float* __restrict__ We2,
             const float* __restrict__ be2, const float* __restrict__ Wc1,
             const float* __restrict__ bc1, const float* __restrict__ Wc2,
             int E, int N)
{
    extern __shared__ float sm[];
    float* We2t = sm;            // [64][72] tf32 bits
    float* Wc1t = sm + 4608;     // [64][72] tf32 bits
    float* w128s = sm + 9216;
    float* be2s = sm + 9280;
    float* bc1s = sm + 9344;
    float* wc2s = sm + 9408;

    const long long* ei64 = (const long long*)ei_raw;
    const int*       ei32 = (const int*)ei_raw;
    const int is64 = g_idx64;

    int tid = threadIdx.x;
    for (int i = tid; i < 4096; i += 256) {
        int k = i >> 6, n = i & 63;
        We2t[k * 72 + n] = __uint_as_float(f2tf(We2[i]));
        Wc1t[k * 72 + n] = __uint_as_float(f2tf(Wc1[i]));
    }
    if (tid < 64) {
        w128s[tid] = We1[128 * 64 + tid];
        be2s[tid] = be2[tid];
        bc1s[tid] = bc1[tid];
        wc2s[tid] = Wc2[tid];
    }
    __syncthreads();

    int w = tid >> 5, lane = tid & 31;
    float* Ms   = sm + SME_MS + w * 2048;     // 32 rows x 64, swizzled
    float* meta = sm + SME_META + w * 256;
    int*   sRow = (int*)meta;                 // 32
    int*   sCol = (int*)meta + 32;            // 32
    float* sMk  = meta + 64;                  // 32
    float* sRad = meta + 96;                  // 32
    float* sCd  = meta + 128;                 // 96

    int qr = lane >> 2, qk = lane & 3;
    float2 w128p = *(float2*)&w128s[2 * lane];

    const int nG = E / 32;   // 40000
    for (int g = blockIdx.x * 8 + w; g < nG; g += gridDim.x * 8) {
        int base = g * 32;
        __syncwarp();  // protect prev-iteration smem reads

        // ---- meta: one edge per lane ----
        {
            long long e = (long long)base + lane;
            int r, c;
            if (is64) { r = (int)ei64[e]; c = (int)ei64[(long long)E + e]; }
            else      { r = ei32[e];      c = ei32[(long long)E + e]; }
            r = min(max(r, 0), N - 1);
            c = min(max(c, 0), N - 1);
            sRow[lane] = r; sCol[lane] = c;
            float dx = coord[r * 3 + 0] - coord[c * 3 + 0];
            float dy = coord[r * 3 + 1] - coord[c * 3 + 1];
            float dz = coord[r * 3 + 2] - coord[c * 3 + 2];
            sCd[lane * 3 + 0] = dx; sCd[lane * 3 + 1] = dy; sCd[lane * 3 + 2] = dz;
            sRad[lane] = dx * dx + dy * dy + dz * dz;
            sMk[lane] = emask[e];
        }
        __syncwarp();

        // ---- combine precomputed layer-1, store tf32 into swizzled Ms ----
#pragma unroll 4
        for (int i = 0; i < 32; i++) {
            int r = sRow[i], c = sCol[i];
            float2 pa = *(const float2*)&g_pre[r * 128 + 2 * lane];
            float2 pb = *(const float2*)&g_pre[c * 128 + 64 + 2 * lane];
            float rad = sRad[i];
            float m0 = silu_t(fmaf(rad, w128p.x, pa.x + pb.x));
            float m1 = silu_t(fmaf(rad, w128p.y, pa.y + pb.y));
            int csw = (2 * lane) ^ ((i & 7) << 2);
            *(uint2*)&Ms[i * 64 + csw] = make_uint2(f2tf(m0), f2tf(m1));
        }
        __syncwarp();

        // ---- layer 2: m = silu(m1 @ We2 + be2) * mask ----
        float acc[2][8][4];
        gemm_mma32(Ms, We2t, be2s, qr, qk, acc);
        __syncwarp();  // all A-frag reads done before overwrite

        // rows handled by this lane: qr, qr+8, qr+16, qr+24
        float mk0 = sMk[qr],      mk1 = sMk[qr + 8];
        float mk2 = sMk[qr + 16], mk3 = sMk[qr + 24];
        int r0 = sRow[qr],      r1 = sRow[qr + 8];
        int r2 = sRow[qr + 16], r3 = sRow[qr + 24];
        const int swst = qr << 2;
#pragma unroll
        for (int nt = 0; nt < 8; nt++) {
            int colb = nt * 8 + 2 * qk;
            int csw = colb ^ swst;
            float m00 = silu_t(acc[0][nt][0]) * mk0;
            float m01 = silu_t(acc[0][nt][1]) * mk0;
            float m10 = silu_t(acc[0][nt][2]) * mk1;
            float m11 = silu_t(acc[0][nt][3]) * mk1;
            float m20 = silu_t(acc[1][nt][0]) * mk2;
            float m21 = silu_t(acc[1][nt][1]) * mk2;
            float m30 = silu_t(acc[1][nt][2]) * mk3;
            float m31 = silu_t(acc[1][nt][3]) * mk3;
            asm volatile("red.global.add.v2.f32 [%0], {%1, %2};"
                         :: "l"(g_agg + r0 * 64 + colb), "f"(m00), "f"(m01) : "memory");
            asm volatile("red.global.add.v2.f32 [%0], {%1, %2};"
                         :: "l"(g_agg + r1 * 64 + colb), "f"(m10), "f"(m11) : "memory");
            asm volatile("red.global.add.v2.f32 [%0], {%1, %2};"
                         :: "l"(g_agg + r2 * 64 + colb), "f"(m20), "f"(m21) : "memory");
            asm volatile("red.global.add.v2.f32 [%0], {%1, %2};"
                         :: "l"(g_agg + r3 * 64 + colb), "f"(m30), "f"(m31) : "memory");
            *(uint2*)&Ms[qr * 64 + csw]          = make_uint2(f2tf(m00), f2tf(m01));
            *(uint2*)&Ms[(qr + 8) * 64 + csw]    = make_uint2(f2tf(m10), f2tf(m11));
            *(uint2*)&Ms[(qr + 16) * 64 + csw]   = make_uint2(f2tf(m20), f2tf(m21));
            *(uint2*)&Ms[(qr + 24) * 64 + csw]   = make_uint2(f2tf(m30), f2tf(m31));
        }
        __syncwarp();

        // ---- coord MLP: cp = silu(m @ Wc1 + bc1) . Wc2 ----
        gemm_mma32(Ms, Wc1t, bc1s, qr, qk, acc);

        float ps0 = 0.0f, ps1 = 0.0f, ps2 = 0.0f, ps3 = 0.0f;
#pragma unroll
        for (int nt = 0; nt < 8; nt++) {
            float2 wc = *(const float2*)&wc2s[nt * 8 + 2 * qk];
            ps0 += silu_t(acc[0][nt][0]) * wc.x + silu_t(acc[0][nt][1]) * wc.y;
            ps1 += silu_t(acc[0][nt][2]) * wc.x + silu_t(acc[0][nt][3]) * wc.y;
            ps2 += silu_t(acc[1][nt][0]) * wc.x + silu_t(acc[1][nt][1]) * wc.y;
            ps3 += silu_t(acc[1][nt][2]) * wc.x + silu_t(acc[1][nt][3]) * wc.y;
        }
        ps0 += __shfl_xor_sync(0xffffffffu, ps0, 1);
        ps0 += __shfl_xor_sync(0xffffffffu, ps0, 2);
        ps1 += __shfl_xor_sync(0xffffffffu, ps1, 1);
        ps1 += __shfl_xor_sync(0xffffffffu, ps1, 2);
        ps2 += __shfl_xor_sync(0xffffffffu, ps2, 1);
        ps2 += __shfl_xor_sync(0xffffffffu, ps2, 2);
        ps3 += __shfl_xor_sync(0xffffffffu, ps3, 1);
        ps3 += __shfl_xor_sync(0xffffffffu, ps3, 2);

        if (qk < 3) {
            atomicAdd(&g_aggc[r0 * 3 + qk], sCd[qr * 3 + qk] * ps0 * mk0);
            atomicAdd(&g_aggc[r1 * 3 + qk], sCd[(qr + 8) * 3 + qk] * ps1 * mk1);
            atomicAdd(&g_aggc[r2 * 3 + qk], sCd[(qr + 16) * 3 + qk] * ps2 * mk2);
            atomicAdd(&g_aggc[r3 * 3 + qk], sCd[(qr + 24) * 3 + qk] * ps3 * mk3);
        } else {
            atomicAdd(&g_cnt[r0], 1.0f);
            atomicAdd(&g_cnt[r1], 1.0f);
            atomicAdd(&g_cnt[r2], 1.0f);
            atomicAdd(&g_cnt[r3], 1.0f);
        }
    }
}

// ---------------- node kernel (fp32 exact) ----------------
__global__ void __launch_bounds__(256)
node_kernel(const float* __restrict__ h, const float* __restrict__ coord,
            const float* __restrict__ Wn1, const float* __restrict__ bn1,
            const float* __restrict__ Wn2, const float* __restrict__ bn2,
            float* __restrict__ out, int N, long long out_size)
{
    extern __shared__ float sm[];
    float* W1t = sm;
    float* W2t = sm + 8192;
    float* b1s = sm + 12288;
    float* b2s = sm + 12352;
    float* NinA = sm + 12416;
    float* HbA  = sm + 20608;

    int tid = threadIdx.x;
    stage_wt(W1t, Wn1, 8192, tid, 256);
    stage_wt(W2t, Wn2, 4096, tid, 256);
    if (tid < 64) { b1s[tid] = bn1[tid]; b2s[tid] = bn2[tid]; }
    __syncthreads();

    int w = tid >> 5, lane = tid & 31;
    float* Nin = NinA + w * 1024;
    float* Hb  = HbA + w * 512;
    ull b10 = pack2(b1s[2 * lane], 0.0f);
    ull b11 = pack2(b1s[2 * lane + 1], 0.0f);
    ull b20 = pack2(b2s[2 * lane], 0.0f);
    ull b21 = pack2(b2s[2 * lane + 1], 0.0f);

    float* hout = out;
    float* cout = out + (long long)N * 64;
    const bool has_coord_out = out_size >= (long long)N * 67;

    const int nGp = N / 8;
    for (int g = blockIdx.x * 8 + w; g < nGp; g += gridDim.x * 8) {
        int base = g * 8;
        __syncwarp();
#pragma unroll
        for (int i = 0; i < 8; i++) {
            int n = base + i;
            *(float2*)&Nin[i * 128 + 2 * lane]      = *(const float2*)&h[(long long)n * 64 + 2 * lane];
            *(float2*)&Nin[i * 128 + 64 + 2 * lane] = *(const float2*)&g_agg[(long long)n * 64 + 2 * lane];
            if (lane < 3 && has_coord_out) {
                float cnt = fmaxf(g_cnt[n], 1.0f);
                cout[n * 3 + lane] = coord[n * 3 + lane] + g_aggc[n * 3 + lane] / cnt;
            }
        }
        __syncwarp();

        ull a0[8], a1[8];
        gemmPK<32, 8, 128>(Nin, W1t, lane, b10, b11, a0, a1);
        __syncwarp();
#pragma unroll
        for (int i = 0; i < 8; i++)
            *(float2*)&Hb[i * 64 + 2 * lane] = make_float2(silu(fin(a0[i])), silu(fin(a1[i])));
        __syncwarp();

        gemmPK<16, 8, 64>(Hb, W2t, lane, b20, b21, a0, a1);
#pragma unroll
        for (int i = 0; i < 8; i++) {
            int n = base + i;
            *(float2*)&hout[(long long)n * 64 + 2 * lane] = make_float2(fin(a0[i]), fin(a1[i]));
        }
    }
}

extern "C" void kernel_launch(void* const* d_in, const int* in_sizes, int n_in,
                              void* d_out, int out_size) {
    const float* h     = (const float*)d_in[0];
    const float* coord = (const float*)d_in[1];
    const void*  ei    = d_in[2];
    const float* emask = (const float*)d_in[3];
    const float* We1   = (const float*)d_in[4];
    const float* be1   = (const float*)d_in[5];
    const float* We2   = (const float*)d_in[6];
    const float* be2   = (const float*)d_in[7];
    const float* Wn1   = (const float*)d_in[8];
    const float* bn1   = (const float*)d_in[9];
    const float* Wn2   = (const float*)d_in[10];
    const float* bn2   = (const float*)d_in[11];
    const float* Wc1   = (const float*)d_in[12];
    const float* bc1   = (const float*)d_in[13];
    const float* Wc2   = (const float*)d_in[14];
    float* out = (float*)d_out;

    int N = in_sizes[0] / 64;   // 40000
    int E = in_sizes[3];        // 1280000

    size_t shP = (size_t)(4096 + 4096 + 64 + 8 * 512) * sizeof(float);
    size_t shE = (size_t)SME_TOT * sizeof(float);
    size_t shN = (size_t)(8192 + 4096 + 64 + 64 + 8 * 1024 + 8 * 512) * sizeof(float);

    cudaFuncSetAttribute(pre_kernel,   cudaFuncAttributeMaxDynamicSharedMemorySize, (int)shP);
    cudaFuncSetAttribute(edge_kernel6, cudaFuncAttributeMaxDynamicSharedMemorySize, (int)shE);
    cudaFuncSetAttribute(node_kernel,  cudaFuncAttributeMaxDynamicSharedMemorySize, (int)shN);

    sniff_kernel<<<1, 256>>>((const int*)ei);
    zero_kernel<<<512, 256>>>(N);
    pre_kernel<<<296, 256, shP>>>(h, We1, be1, N);
    edge_kernel6<<<296, 256, shE>>>(coord, ei, emask,
                                    We1, We2, be2, Wc1, bc1, Wc2, E, N);
    node_kernel<<<296, 256, shN>>>(h, coord, Wn1, bn1, Wn2, bn2, out, N,
                                   (long long)out_size);
}

// round 12
// speedup vs baseline: 4.9066x; 1.0346x over previous
#include <cuda_runtime.h>

// Problem constants: N=40000, F=64, H=64, E=1280000
#define MAXN 40000

__device__ float g_pre[MAXN * 128]; // [P_A = h@We1_top + be1 | P_B = h@We1_bot]
__device__ float g_agg[MAXN * 64];  // sum of m per row-node
__device__ float g_aggc[MAXN * 3];  // sum of trans per row-node
__device__ float g_cnt[MAXN];       // edge count per row-node
__device__ int   g_idx64;           // edge_index dtype flag

typedef unsigned long long ull;
typedef unsigned int uint;

__device__ __forceinline__ float silu(float x) {
    return __fdividef(x, 1.0f + __expf(-x));
}
// 1-MUFU silu: x/2 * (1 + tanh(x/2))  (validated in R9: no rel_err change)
__device__ __forceinline__ float silu_t(float x) {
    float t;
    asm("tanh.approx.f32 %0, %1;" : "=f"(t) : "f"(x * 0.5f));
    return fmaf(0.5f * x, t, 0.5f * x);
}
__device__ __forceinline__ ull pack2(float lo, float hi) {
    ull r; asm("mov.b64 %0, {%1, %2};" : "=l"(r) : "f"(lo), "f"(hi)); return r;
}
__device__ __forceinline__ float2 unpack2(ull v) {
    float2 f; asm("mov.b64 {%0, %1}, %2;" : "=f"(f.x), "=f"(f.y) : "l"(v)); return f;
}
__device__ __forceinline__ void fma2(ull& d, ull a, ull b) {
    asm("fma.rn.f32x2 %0, %1, %2, %3;" : "=l"(d) : "l"(a), "l"(b), "l"(d));
}
__device__ __forceinline__ float fin(ull a) { float2 u = unpack2(a); return u.x + u.y; }

__device__ __forceinline__ uint f2tf(float x) {
    uint r; asm("cvt.rna.tf32.f32 %0, %1;" : "=r"(r) : "f"(x)); return r;
}
__device__ __forceinline__ void mma_tf32(float d[4], const uint a[4], const uint b[2]) {
    asm("mma.sync.aligned.m16n8k8.row.col.f32.tf32.tf32.f32 "
        "{%0,%1,%2,%3}, {%4,%5,%6,%7}, {%8,%9}, {%0,%1,%2,%3};"
        : "+f"(d[0]), "+f"(d[1]), "+f"(d[2]), "+f"(d[3])
        : "r"(a[0]), "r"(a[1]), "r"(a[2]), "r"(a[3]), "r"(b[0]), "r"(b[1]));
}

// ---------------- dtype sniff ----------------
__global__ void sniff_kernel(const int* __restrict__ ei32) {
    __shared__ int nonzero;
    if (threadIdx.x == 0) nonzero = 0;
    __syncthreads();
    for (int i = threadIdx.x; i < 1024; i += blockDim.x)
        if (ei32[2 * i + 1] != 0) atomicOr(&nonzero, 1);
    __syncthreads();
    if (threadIdx.x == 0) g_idx64 = (nonzero == 0) ? 1 : 0;
}

__global__ void zero_kernel(int n_nodes) {
    int idx = blockIdx.x * blockDim.x + threadIdx.x;
    int stride = gridDim.x * blockDim.x;
    for (int i = idx; i < n_nodes * 64; i += stride) g_agg[i] = 0.0f;
    for (int i = idx; i < n_nodes * 3; i += stride) g_aggc[i] = 0.0f;
    for (int i = idx; i < n_nodes; i += stride) g_cnt[i] = 0.0f;
}

// ---------------- transposed weight staging (scalar path) ----------------
__device__ __forceinline__ void stage_wt(float* dst, const float* __restrict__ W,
                                         int elems, int tid, int nt) {
    for (int i = tid; i < elems; i += nt) {
        int j = i >> 7, rem = i & 127, l = rem >> 2, s = rem & 3;
        dst[i] = W[(2 * j + (s & 1)) * 64 + 2 * l + (s >> 1)];
    }
}

// ---------------- k-pair packed scalar GEMM (pre/node kernels) ----------------
template<int K4, int ROWS, int LDX>
__device__ __forceinline__ void gemmPK(const float* __restrict__ Xs,
                                       const float* __restrict__ Wt,
                                       int lane, ull bi0, ull bi1,
                                       ull acc0[ROWS], ull acc1[ROWS]) {
#pragma unroll
    for (int i = 0; i < ROWS; i++) { acc0[i] = bi0; acc1[i] = bi1; }
#pragma unroll 2
    for (int kc = 0; kc < K4; kc++) {
        const float* wp = Wt + kc * 256 + lane * 4;
        ulonglong2 wa = *(const ulonglong2*)(wp);
        ulonglong2 wb = *(const ulonglong2*)(wp + 128);
#pragma unroll
        for (int i = 0; i < ROWS; i++) {
            ulonglong2 xv = *(const ulonglong2*)(Xs + i * LDX + kc * 4);
            fma2(acc0[i], xv.x, wa.x);
            fma2(acc1[i], xv.x, wa.y);
            fma2(acc0[i], xv.y, wb.x);
            fma2(acc1[i], xv.y, wb.y);
        }
    }
}

// ---------------- per-node precompute ----------------
__global__ void __launch_bounds__(256)
pre_kernel(const float* __restrict__ h, const float* __restrict__ We1,
           const float* __restrict__ be1, int N)
{
    extern __shared__ float sm[];
    float* WAt  = sm;
    float* WBt  = sm + 4096;
    float* be1s = sm + 8192;
    float* HtA  = sm + 8256;

    int tid = threadIdx.x;
    stage_wt(WAt, We1, 4096, tid, 256);
    stage_wt(WBt, We1 + 4096, 4096, tid, 256);
    if (tid < 64) be1s[tid] = be1[tid];
    __syncthreads();

    int w = tid >> 5, lane = tid & 31;
    float* Ht = HtA + w * 512;
    ull b0 = pack2(be1s[2 * lane], 0.0f);
    ull b1 = pack2(be1s[2 * lane + 1], 0.0f);
    ull z = pack2(0.0f, 0.0f);

    const int nGp = N / 8;
    for (int g = blockIdx.x * 8 + w; g < nGp; g += gridDim.x * 8) {
        int base = g * 8;
        __syncwarp();
#pragma unroll
        for (int i = 0; i < 8; i++)
            *(float2*)&Ht[i * 64 + 2 * lane] = *(const float2*)&h[(base + i) * 64 + 2 * lane];
        __syncwarp();

        ull a0[8], a1[8];
        gemmPK<16, 8, 64>(Ht, WAt, lane, b0, b1, a0, a1);
#pragma unroll
        for (int i = 0; i < 8; i++)
            *(float2*)&g_pre[(base + i) * 128 + 2 * lane] = make_float2(fin(a0[i]), fin(a1[i]));
        gemmPK<16, 8, 64>(Ht, WBt, lane, z, z, a0, a1);
#pragma unroll
        for (int i = 0; i < 8; i++)
            *(float2*)&g_pre[(base + i) * 128 + 64 + 2 * lane] = make_float2(fin(a0[i]), fin(a1[i]));
    }
}

// ---------------- edge kernel: mma.sync tf32, M=16, 10 warps/block ----------------
// smem floats:
//   We2t [64][72]=4608 @0 | Wc1t 4608 @4608 | w128s 64 @9216 | be2s 64 @9280
//   bc1s 64 @9344 | wc2s 64 @9408 | Ms 10*16*64=10240 @9472 | meta 10*128 @19712
// total 20992 floats = 83968 B  (2 blocks/SM = 164 KB <= 228; 640 thr @102 regs fills RF)
#define EWARPS   10
#define ETHREADS 320
#define SME_MS   9472
#define SME_META 19712
#define SME_TOT  20992

// Ms swizzle: addr(row, col) = row*64 + (col ^ ((row&7)<<2))
// M=16 warp GEMM on swizzled Ms.
__device__ __forceinline__ void gemm_mma16s(const float* __restrict__ Ms,
                                            const float* __restrict__ Wt,
                                            const float* __restrict__ bias,
                                            int qr, int qk, float acc[8][4]) {
#pragma unroll
    for (int nt = 0; nt < 8; nt++) {
        float2 b = *(const float2*)&bias[nt * 8 + 2 * qk];
        acc[nt][0] = b.x; acc[nt][1] = b.y; acc[nt][2] = b.x; acc[nt][3] = b.y;
    }
    const int sw = qr << 2;
    const float* r0 = Ms + qr * 64;
#pragma unroll
    for (int kt = 0; kt < 8; kt++) {
        int c0 = (kt * 8 + qk) ^ sw;
        int c1 = (kt * 8 + qk + 4) ^ sw;
        uint a[4];
        a[0] = __float_as_uint(r0[c0]);
        a[1] = __float_as_uint(r0[512 + c0]);   // row qr+8 (same swizzle: (qr+8)&7 == qr)
        a[2] = __float_as_uint(r0[c1]);
        a[3] = __float_as_uint(r0[512 + c1]);
        const float* bp = Wt + (kt * 8 + qk) * 72 + qr;
#pragma unroll
        for (int nt = 0; nt < 8; nt++) {
            uint b[2];
            b[0] = __float_as_uint(bp[nt * 8]);
            b[1] = __float_as_uint(bp[nt * 8 + 4 * 72]);
            mma_tf32(acc[nt], a, b);
        }
    }
}

__global__ void __launch_bounds__(ETHREADS, 2)
edge_kernel7(const float* __restrict__ coord,
             const void* __restrict__ ei_raw, const float* __restrict__ emask,
             const float* __restrict__ We1, const float* __restrict__ We2,
             const float* __restrict__ be2, const float* __restrict__ Wc1,
             const float* __restrict__ bc1, const float* __restrict__ Wc2,
             int E, int N)
{
    extern __shared__ float sm[];
    float* We2t = sm;            // [64][72] tf32 bits
    float* Wc1t = sm + 4608;     // [64][72] tf32 bits
    float* w128s = sm + 9216;
    float* be2s = sm + 9280;
    float* bc1s = sm + 9344;
    float* wc2s = sm + 9408;

    const long long* ei64 = (const long long*)ei_raw;
    const int*       ei32 = (const int*)ei_raw;
    const int is64 = g_idx64;

    int tid = threadIdx.x;
    for (int i = tid; i < 4096; i += ETHREADS) {
        int k = i >> 6, n = i & 63;
        We2t[k * 72 + n] = __uint_as_float(f2tf(We2[i]));
        Wc1t[k * 72 + n] = __uint_as_float(f2tf(Wc1[i]));
    }
    if (tid < 64) {
        w128s[tid] = We1[128 * 64 + tid];
        be2s[tid] = be2[tid];
        bc1s[tid] = bc1[tid];
        wc2s[tid] = Wc2[tid];
    }
    __syncthreads();

    int w = tid >> 5, lane = tid & 31;
    float* Ms   = sm + SME_MS + w * 1024;     // 16 rows x 64, swizzled
    float* meta = sm + SME_META + w * 128;
    int*   sRow = (int*)meta;                 // 16
    int*   sCol = (int*)meta + 16;            // 16
    float* sMk  = meta + 32;                  // 16
    float* sRad = meta + 48;                  // 16
    float* sCd  = meta + 64;                  // 48

    int qr = lane >> 2, qk = lane & 3;
    float2 w128p = *(float2*)&w128s[2 * lane];

    const int nG = E / 16;   // 80000
    for (int g = blockIdx.x * EWARPS + w; g < nG; g += gridDim.x * EWARPS) {
        int base = g * 16;
        __syncwarp();  // protect prev-iteration smem reads

        // ---- meta (lanes 0..15, one edge each) ----
        if (lane < 16) {
            long long e = (long long)base + lane;
            int r, c;
            if (is64) { r = (int)ei64[e]; c = (int)ei64[(long long)E + e]; }
            else      { r = ei32[e];      c = ei32[(long long)E + e]; }
            r = min(max(r, 0), N - 1);
            c = min(max(c, 0), N - 1);
            sRow[lane] = r; sCol[lane] = c;
            float dx = coord[r * 3 + 0] - coord[c * 3 + 0];
            float dy = coord[r * 3 + 1] - coord[c * 3 + 1];
            float dz = coord[r * 3 + 2] - coord[c * 3 + 2];
            sCd[lane * 3 + 0] = dx; sCd[lane * 3 + 1] = dy; sCd[lane * 3 + 2] = dz;
            sRad[lane] = dx * dx + dy * dy + dz * dz;
            sMk[lane] = emask[e];
        }
        __syncwarp();

        // ---- combine precomputed layer-1, store tf32 into swizzled Ms ----
#pragma unroll 4
        for (int i = 0; i < 16; i++) {
            int r = sRow[i], c = sCol[i];
            float2 pa = *(const float2*)&g_pre[r * 128 + 2 * lane];
            float2 pb = *(const float2*)&g_pre[c * 128 + 64 + 2 * lane];
            float rad = sRad[i];
            float m0 = silu_t(fmaf(rad, w128p.x, pa.x + pb.x));
            float m1 = silu_t(fmaf(rad, w128p.y, pa.y + pb.y));
            int csw = (2 * lane) ^ ((i & 7) << 2);
            *(uint2*)&Ms[i * 64 + csw] = make_uint2(f2tf(m0), f2tf(m1));
        }
        __syncwarp();

        // ---- layer 2: m = silu(m1 @ We2 + be2) * mask ----
        float acc[8][4];
        gemm_mma16s(Ms, We2t, be2s, qr, qk, acc);
        __syncwarp();  // all A-frag reads done before overwrite

        float mk0 = sMk[qr], mk1 = sMk[qr + 8];
        int r0 = sRow[qr], r1 = sRow[qr + 8];
        const int swst = qr << 2;
#pragma unroll
        for (int nt = 0; nt < 8; nt++) {
            int colb = nt * 8 + 2 * qk;
            int csw = colb ^ swst;
            float m00 = silu_t(acc[nt][0]) * mk0;
            float m01 = silu_t(acc[nt][1]) * mk0;
            float m10 = silu_t(acc[nt][2]) * mk1;
            float m11 = silu_t(acc[nt][3]) * mk1;
            asm volatile("red.global.add.v2.f32 [%0], {%1, %2};"
                         :: "l"(g_agg + r0 * 64 + colb), "f"(m00), "f"(m01) : "memory");
            asm volatile("red.global.add.v2.f32 [%0], {%1, %2};"
                         :: "l"(g_agg + r1 * 64 + colb), "f"(m10), "f"(m11) : "memory");
            *(uint2*)&Ms[qr * 64 + csw]       = make_uint2(f2tf(m00), f2tf(m01));
            *(uint2*)&Ms[(qr + 8) * 64 + csw] = make_uint2(f2tf(m10), f2tf(m11));
        }
        __syncwarp();

        // ---- coord MLP: cp = silu(m @ Wc1 + bc1) . Wc2 ----
        gemm_mma16s(Ms, Wc1t, bc1s, qr, qk, acc);

        float ps0 = 0.0f, ps1 = 0.0f;
#pragma unroll
        for (int nt = 0; nt < 8; nt++) {
            float2 wc = *(const float2*)&wc2s[nt * 8 + 2 * qk];
            ps0 += silu_t(acc[nt][0]) * wc.x + silu_t(acc[nt][1]) * wc.y;
            ps1 += silu_t(acc[nt][2]) * wc.x + silu_t(acc[nt][3]) * wc.y;
        }
        ps0 += __shfl_xor_sync(0xffffffffu, ps0, 1);
        ps0 += __shfl_xor_sync(0xffffffffu, ps0, 2);
        ps1 += __shfl_xor_sync(0xffffffffu, ps1, 1);
        ps1 += __shfl_xor_sync(0xffffffffu, ps1, 2);

        if (qk < 3) {
            atomicAdd(&g_aggc[r0 * 3 + qk], sCd[qr * 3 + qk] * ps0 * mk0);
            atomicAdd(&g_aggc[r1 * 3 + qk], sCd[(qr + 8) * 3 + qk] * ps1 * mk1);
        } else {
            atomicAdd(&g_cnt[r0], 1.0f);
            atomicAdd(&g_cnt[r1], 1.0f);
        }
    }
}

// ---------------- node kernel (fp32 exact) ----------------
__global__ void __launch_bounds__(256)
node_kernel(const float* __restrict__ h, const float* __restrict__ coord,
            const float* __restrict__ Wn1, const float* __restrict__ bn1,
            const float* __restrict__ Wn2, const float* __restrict__ bn2,
            float* __restrict__ out, int N, long long out_size)
{
    extern __shared__ float sm[];
    float* W1t = sm;
    float* W2t = sm + 8192;
    float* b1s = sm + 12288;
    float* b2s = sm + 12352;
    float* NinA = sm + 12416;
    float* HbA  = sm + 20608;

    int tid = threadIdx.x;
    stage_wt(W1t, Wn1, 8192, tid, 256);
    stage_wt(W2t, Wn2, 4096, tid, 256);
    if (tid < 64) { b1s[tid] = bn1[tid]; b2s[tid] = bn2[tid]; }
    __syncthreads();

    int w = tid >> 5, lane = tid & 31;
    float* Nin = NinA + w * 1024;
    float* Hb  = HbA + w * 512;
    ull b10 = pack2(b1s[2 * lane], 0.0f);
    ull b11 = pack2(b1s[2 * lane + 1], 0.0f);
    ull b20 = pack2(b2s[2 * lane], 0.0f);
    ull b21 = pack2(b2s[2 * lane + 1], 0.0f);

    float* hout = out;
    float* cout = out + (long long)N * 64;
    const bool has_coord_out = out_size >= (long long)N * 67;

    const int nGp = N / 8;
    for (int g = blockIdx.x * 8 + w; g < nGp; g += gridDim.x * 8) {
        int base = g * 8;
        __syncwarp();
#pragma unroll
        for (int i = 0; i < 8; i++) {
            int n = base + i;
            *(float2*)&Nin[i * 128 + 2 * lane]      = *(const float2*)&h[(long long)n * 64 + 2 * lane];
            *(float2*)&Nin[i * 128 + 64 + 2 * lane] = *(const float2*)&g_agg[(long long)n * 64 + 2 * lane];
            if (lane < 3 && has_coord_out) {
                float cnt = fmaxf(g_cnt[n], 1.0f);
                cout[n * 3 + lane] = coord[n * 3 + lane] + g_aggc[n * 3 + lane] / cnt;
            }
        }
        __syncwarp();

        ull a0[8], a1[8];
        gemmPK<32, 8, 128>(Nin, W1t, lane, b10, b11, a0, a1);
        __syncwarp();
#pragma unroll
        for (int i = 0; i < 8; i++)
            *(float2*)&Hb[i * 64 + 2 * lane] = make_float2(silu(fin(a0[i])), silu(fin(a1[i])));
        __syncwarp();

        gemmPK<16, 8, 64>(Hb, W2t, lane, b20, b21, a0, a1);
#pragma unroll
        for (int i = 0; i < 8; i++) {
            int n = base + i;
            *(float2*)&hout[(long long)n * 64 + 2 * lane] = make_float2(fin(a0[i]), fin(a1[i]));
        }
    }
}

extern "C" void kernel_launch(void* const* d_in, const int* in_sizes, int n_in,
                              void* d_out, int out_size) {
    const float* h     = (const float*)d_in[0];
    const float* coord = (const float*)d_in[1];
    const void*  ei    = d_in[2];
    const float* emask = (const float*)d_in[3];
    const float* We1   = (const float*)d_in[4];
    const float* be1   = (const float*)d_in[5];
    const float* We2   = (const float*)d_in[6];
    const float* be2   = (const float*)d_in[7];
    const float* Wn1   = (const float*)d_in[8];
    const float* bn1   = (const float*)d_in[9];
    const float* Wn2   = (const float*)d_in[10];
    const float* bn2   = (const float*)d_in[11];
    const float* Wc1   = (const float*)d_in[12];
    const float* bc1   = (const float*)d_in[13];
    const float* Wc2   = (const float*)d_in[14];
    float* out = (float*)d_out;

    int N = in_sizes[0] / 64;   // 40000
    int E = in_sizes[3];        // 1280000

    size_t shP = (size_t)(4096 + 4096 + 64 + 8 * 512) * sizeof(float);
    size_t shE = (size_t)SME_TOT * sizeof(float);
    size_t shN = (size_t)(8192 + 4096 + 64 + 64 + 8 * 1024 + 8 * 512) * sizeof(float);

    cudaFuncSetAttribute(pre_kernel,   cudaFuncAttributeMaxDynamicSharedMemorySize, (int)shP);
    cudaFuncSetAttribute(edge_kernel7, cudaFuncAttributeMaxDynamicSharedMemorySize, (int)shE);
    cudaFuncSetAttribute(node_kernel,  cudaFuncAttributeMaxDynamicSharedMemorySize, (int)shN);

    sniff_kernel<<<1, 256>>>((const int*)ei);
    zero_kernel<<<512, 256>>>(N);
    pre_kernel<<<296, 256, shP>>>(h, We1, be1, N);
    edge_kernel7<<<296, ETHREADS, shE>>>(coord, ei, emask,
                                         We1, We2, be2, Wc1, bc1, Wc2, E, N);
    node_kernel<<<296, 256, shN>>>(h, coord, Wn1, bn1, Wn2, bn2, out, N,
                                   (long long)out_size);
}

// round 16
// speedup vs baseline: 5.0063x; 1.0203x over previous
#include <cuda_runtime.h>

// Problem constants: N=40000, F=64, H=64, E=1280000
#define MAXN 40000

__device__ float g_pre[MAXN * 128]; // [P_A = h@We1_top + be1 | P_B = h@We1_bot]
__device__ float g_agg[MAXN * 64];  // sum of m per row-node
__device__ float g_aggc[MAXN * 3];  // sum of trans per row-node
__device__ float g_cnt[MAXN];       // edge count per row-node
__device__ int   g_idx64;           // edge_index dtype flag

typedef unsigned long long ull;
typedef unsigned int uint;

__device__ __forceinline__ float silu(float x) {
    return __fdividef(x, 1.0f + __expf(-x));
}
// 1-MUFU silu: x/2 * (1 + tanh(x/2))  (validated R9: no rel_err change)
__device__ __forceinline__ float silu_t(float x) {
    float t;
    asm("tanh.approx.f32 %0, %1;" : "=f"(t) : "f"(x * 0.5f));
    return fmaf(0.5f * x, t, 0.5f * x);
}
__device__ __forceinline__ ull pack2(float lo, float hi) {
    ull r; asm("mov.b64 %0, {%1, %2};" : "=l"(r) : "f"(lo), "f"(hi)); return r;
}
__device__ __forceinline__ float2 unpack2(ull v) {
    float2 f; asm("mov.b64 {%0, %1}, %2;" : "=f"(f.x), "=f"(f.y) : "l"(v)); return f;
}
__device__ __forceinline__ void fma2(ull& d, ull a, ull b) {
    asm("fma.rn.f32x2 %0, %1, %2, %3;" : "=l"(d) : "l"(a), "l"(b), "l"(d));
}
__device__ __forceinline__ float fin(ull a) { float2 u = unpack2(a); return u.x + u.y; }

__device__ __forceinline__ uint f2tf(float x) {
    uint r; asm("cvt.rna.tf32.f32 %0, %1;" : "=r"(r) : "f"(x)); return r;
}
__device__ __forceinline__ void mma_tf32(float d[4], const uint a[4], uint b0, uint b1) {
    asm("mma.sync.aligned.m16n8k8.row.col.f32.tf32.tf32.f32 "
        "{%0,%1,%2,%3}, {%4,%5,%6,%7}, {%8,%9}, {%0,%1,%2,%3};"
        : "+f"(d[0]), "+f"(d[1]), "+f"(d[2]), "+f"(d[3])
        : "r"(a[0]), "r"(a[1]), "r"(a[2]), "r"(a[3]), "r"(b0), "r"(b1));
}

// ---------------- dtype sniff ----------------
__global__ void sniff_kernel(const int* __restrict__ ei32) {
    __shared__ int nonzero;
    if (threadIdx.x == 0) nonzero = 0;
    __syncthreads();
    for (int i = threadIdx.x; i < 1024; i += blockDim.x)
        if (ei32[2 * i + 1] != 0) atomicOr(&nonzero, 1);
    __syncthreads();
    if (threadIdx.x == 0) g_idx64 = (nonzero == 0) ? 1 : 0;
}

__global__ void zero_kernel(int n_nodes) {
    int idx = blockIdx.x * blockDim.x + threadIdx.x;
    int stride = gridDim.x * blockDim.x;
    for (int i = idx; i < n_nodes * 64; i += stride) g_agg[i] = 0.0f;
    for (int i = idx; i < n_nodes * 3; i += stride) g_aggc[i] = 0.0f;
    for (int i = idx; i < n_nodes; i += stride) g_cnt[i] = 0.0f;
}

// ---------------- transposed weight staging (scalar path) ----------------
__device__ __forceinline__ void stage_wt(float* dst, const float* __restrict__ W,
                                         int elems, int tid, int nt) {
    for (int i = tid; i < elems; i += nt) {
        int j = i >> 7, rem = i & 127, l = rem >> 2, s = rem & 3;
        dst[i] = W[(2 * j + (s & 1)) * 64 + 2 * l + (s >> 1)];
    }
}

// ---------------- k-pair packed scalar GEMM (pre/node kernels) ----------------
template<int K4, int ROWS, int LDX>
__device__ __forceinline__ void gemmPK(const float* __restrict__ Xs,
                                       const float* __restrict__ Wt,
                                       int lane, ull bi0, ull bi1,
                                       ull acc0[ROWS], ull acc1[ROWS]) {
#pragma unroll
    for (int i = 0; i < ROWS; i++) { acc0[i] = bi0; acc1[i] = bi1; }
#pragma unroll 2
    for (int kc = 0; kc < K4; kc++) {
        const float* wp = Wt + kc * 256 + lane * 4;
        ulonglong2 wa = *(const ulonglong2*)(wp);
        ulonglong2 wb = *(const ulonglong2*)(wp + 128);
#pragma unroll
        for (int i = 0; i < ROWS; i++) {
            ulonglong2 xv = *(const ulonglong2*)(Xs + i * LDX + kc * 4);
            fma2(acc0[i], xv.x, wa.x);
            fma2(acc1[i], xv.x, wa.y);
            fma2(acc0[i], xv.y, wb.x);
            fma2(acc1[i], xv.y, wb.y);
        }
    }
}

// ---------------- per-node precompute ----------------
__global__ void __launch_bounds__(256)
pre_kernel(const float* __restrict__ h, const float* __restrict__ We1,
           const float* __restrict__ be1, int N)
{
    extern __shared__ float sm[];
    float* WAt  = sm;
    float* WBt  = sm + 4096;
    float* be1s = sm + 8192;
    float* HtA  = sm + 8256;

    int tid = threadIdx.x;
    stage_wt(WAt, We1, 4096, tid, 256);
    stage_wt(WBt, We1 + 4096, 4096, tid, 256);
    if (tid < 64) be1s[tid] = be1[tid];
    __syncthreads();

    int w = tid >> 5, lane = tid & 31;
    float* Ht = HtA + w * 512;
    ull b0 = pack2(be1s[2 * lane], 0.0f);
    ull b1 = pack2(be1s[2 * lane + 1], 0.0f);
    ull z = pack2(0.0f, 0.0f);

    const int nGp = N / 8;
    for (int g = blockIdx.x * 8 + w; g < nGp; g += gridDim.x * 8) {
        int base = g * 8;
        __syncwarp();
#pragma unroll
        for (int i = 0; i < 8; i++)
            *(float2*)&Ht[i * 64 + 2 * lane] = *(const float2*)&h[(base + i) * 64 + 2 * lane];
        __syncwarp();

        ull a0[8], a1[8];
        gemmPK<16, 8, 64>(Ht, WAt, lane, b0, b1, a0, a1);
#pragma unroll
        for (int i = 0; i < 8; i++)
            *(float2*)&g_pre[(base + i) * 128 + 2 * lane] = make_float2(fin(a0[i]), fin(a1[i]));
        gemmPK<16, 8, 64>(Ht, WBt, lane, z, z, a0, a1);
#pragma unroll
        for (int i = 0; i < 8; i++)
            *(float2*)&g_pre[(base + i) * 128 + 64 + 2 * lane] = make_float2(fin(a0[i]), fin(a1[i]));
    }
}

// ---------------- edge kernel: mma.sync tf32, frag-packed B ----------------
// B frag layout (loop-invariant weights prestaged per-lane):
//   Bq[((kt*4 + ntp)*32 + lane)*4 + {0..3}] =
//     { W[8kt+qk][16ntp+qr], W[8kt+qk+4][16ntp+qr],
//       W[8kt+qk][16ntp+8+qr], W[8kt+qk+4][16ntp+8+qr] }  (tf32 bits)
// One LDS.128 per (kt,ntp) feeds two mma n-tiles.
// smem floats:
//   We2q 4096 @0 | Wc1q 4096 @4096 | w128s 64 @8192 | be2s 64 @8256
//   bc1s 64 @8320 | wc2s 64 @8384 | Ms 10*16*64=10240 @8448 | meta 10*128 @18688
// total 19968 floats = 79872 B  (2 blocks/SM = 160 KB <= 228)
#define EWARPS   10
#define ETHREADS 320
#define SME_MS   8448
#define SME_META 18688
#define SME_TOT  19968

// Ms swizzle: addr(row, col) = row*64 + (col ^ ((row&7)<<2))
__device__ __forceinline__ void gemm_mma16q(const float* __restrict__ Ms,
                                            const float* __restrict__ Bq,
                                            const float* __restrict__ bias,
                                            int qr, int qk, int lane, float acc[8][4]) {
#pragma unroll
    for (int nt = 0; nt < 8; nt++) {
        float2 b = *(const float2*)&bias[nt * 8 + 2 * qk];
        acc[nt][0] = b.x; acc[nt][1] = b.y; acc[nt][2] = b.x; acc[nt][3] = b.y;
    }
    const int sw = qr << 2;
    const float* r0 = Ms + qr * 64;
    const float* bq0 = Bq + lane * 4;
#pragma unroll
    for (int kt = 0; kt < 8; kt++) {
        int c0 = (kt * 8 + qk) ^ sw;
        int c1 = (kt * 8 + qk + 4) ^ sw;
        uint a[4];
        a[0] = __float_as_uint(r0[c0]);
        a[1] = __float_as_uint(r0[512 + c0]);   // row qr+8 (same swizzle)
        a[2] = __float_as_uint(r0[c1]);
        a[3] = __float_as_uint(r0[512 + c1]);
#pragma unroll
        for (int ntp = 0; ntp < 4; ntp++) {
            float4 bq = *(const float4*)(bq0 + (kt * 4 + ntp) * 128);
            mma_tf32(acc[2 * ntp],     a, __float_as_uint(bq.x), __float_as_uint(bq.y));
            mma_tf32(acc[2 * ntp + 1], a, __float_as_uint(bq.z), __float_as_uint(bq.w));
        }
    }
}

__global__ void __launch_bounds__(ETHREADS, 2)
edge_kernel8(const float* __restrict__ coord,
             const void* __restrict__ ei_raw, const float* __restrict__ emask,
             const float* __restrict__ We1, const float* __restrict__ We2,
             const float* __restrict__ be2, const float* __restrict__ Wc1,
             const float* __restrict__ bc1, const float* __restrict__ Wc2,
             int E, int N)
{
    extern __shared__ float sm[];
    float* We2q = sm;            // frag-packed tf32 bits
    float* Wc1q = sm + 4096;     // frag-packed tf32 bits
    float* w128s = sm + 8192;
    float* be2s = sm + 8256;
    float* bc1s = sm + 8320;
    float* wc2s = sm + 8384;

    const long long* ei64 = (const long long*)ei_raw;
    const int*       ei32 = (const int*)ei_raw;
    const int is64 = g_idx64;

    int tid = threadIdx.x;
    // stage weights into per-lane fragment order
    for (int i = tid; i < 4096; i += ETHREADS) {
        int kt = i >> 9, ntp = (i >> 7) & 3, l = (i >> 2) & 31, j = i & 3;
        int lqr = l >> 2, lqk = l & 3;
        int k = kt * 8 + lqk + (j & 1) * 4;
        int c = ntp * 16 + (j >> 1) * 8 + lqr;
        We2q[i] = __uint_as_float(f2tf(We2[k * 64 + c]));
        Wc1q[i] = __uint_as_float(f2tf(Wc1[k * 64 + c]));
    }
    if (tid < 64) {
        w128s[tid] = We1[128 * 64 + tid];
        be2s[tid] = be2[tid];
        bc1s[tid] = bc1[tid];
        wc2s[tid] = Wc2[tid];
    }
    __syncthreads();

    int w = tid >> 5, lane = tid & 31;
    float* Ms   = sm + SME_MS + w * 1024;     // 16 rows x 64, swizzled
    float* meta = sm + SME_META + w * 128;
    int*   sRow = (int*)meta;                 // 16
    int*   sCol = (int*)meta + 16;            // 16
    float* sMk  = meta + 32;                  // 16
    float* sRad = meta + 48;                  // 16
    float* sCd  = meta + 64;                  // 48

    int qr = lane >> 2, qk = lane & 3;
    float2 w128p = *(float2*)&w128s[2 * lane];

    const int nG = E / 16;   // 80000
    for (int g = blockIdx.x * EWARPS + w; g < nG; g += gridDim.x * EWARPS) {
        int base = g * 16;
        __syncwarp();  // protect prev-iteration smem reads

        // ---- meta (lanes 0..15, one edge each) ----
        if (lane < 16) {
            long long e = (long long)base + lane;
            int r, c;
            if (is64) { r = (int)ei64[e]; c = (int)ei64[(long long)E + e]; }
            else      { r = ei32[e];      c = ei32[(long long)E + e]; }
            r = min(max(r, 0), N - 1);
            c = min(max(c, 0), N - 1);
            sRow[lane] = r; sCol[lane] = c;
            float dx = coord[r * 3 + 0] - coord[c * 3 + 0];
            float dy = coord[r * 3 + 1] - coord[c * 3 + 1];
            float dz = coord[r * 3 + 2] - coord[c * 3 + 2];
            sCd[lane * 3 + 0] = dx; sCd[lane * 3 + 1] = dy; sCd[lane * 3 + 2] = dz;
            sRad[lane] = dx * dx + dy * dy + dz * dz;
            sMk[lane] = emask[e];
        }
        __syncwarp();

        // ---- combine precomputed layer-1, store tf32 into swizzled Ms ----
#pragma unroll 4
        for (int i = 0; i < 16; i++) {
            int r = sRow[i], c = sCol[i];
            float2 pa = *(const float2*)&g_pre[r * 128 + 2 * lane];
            float2 pb = *(const float2*)&g_pre[c * 128 + 64 + 2 * lane];
            float rad = sRad[i];
            float m0 = silu_t(fmaf(rad, w128p.x, pa.x + pb.x));
            float m1 = silu_t(fmaf(rad, w128p.y, pa.y + pb.y));
            int csw = (2 * lane) ^ ((i & 7) << 2);
            *(uint2*)&Ms[i * 64 + csw] = make_uint2(f2tf(m0), f2tf(m1));
        }
        __syncwarp();

        // ---- layer 2: m = silu(m1 @ We2 + be2) * mask ----
        float acc[8][4];
        gemm_mma16q(Ms, We2q, be2s, qr, qk, lane, acc);
        __syncwarp();  // all A-frag reads done before overwrite

        float mk0 = sMk[qr], mk1 = sMk[qr + 8];
        int r0 = sRow[qr], r1 = sRow[qr + 8];
        const int swst = qr << 2;
#pragma unroll
        for (int nt = 0; nt < 8; nt++) {
            int colb = nt * 8 + 2 * qk;
            int csw = colb ^ swst;
            float m00 = silu_t(acc[nt][0]) * mk0;
            float m01 = silu_t(acc[nt][1]) * mk0;
            float m10 = silu_t(acc[nt][2]) * mk1;
            float m11 = silu_t(acc[nt][3]) * mk1;
            asm volatile("red.global.add.v2.f32 [%0], {%1, %2};"
                         :: "l"(g_agg + r0 * 64 + colb), "f"(m00), "f"(m01) : "memory");
            asm volatile("red.global.add.v2.f32 [%0], {%1, %2};"
                         :: "l"(g_agg + r1 * 64 + colb), "f"(m10), "f"(m11) : "memory");
            *(uint2*)&Ms[qr * 64 + csw]       = make_uint2(f2tf(m00), f2tf(m01));
            *(uint2*)&Ms[(qr + 8) * 64 + csw] = make_uint2(f2tf(m10), f2tf(m11));
        }
        __syncwarp();

        // ---- coord MLP: cp = silu(m @ Wc1 + bc1) . Wc2 ----
        gemm_mma16q(Ms, Wc1q, bc1s, qr, qk, lane, acc);

        float ps0 = 0.0f, ps1 = 0.0f;
#pragma unroll
        for (int nt = 0; nt < 8; nt++) {
            float2 wc = *(const float2*)&wc2s[nt * 8 + 2 * qk];
            ps0 += silu_t(acc[nt][0]) * wc.x + silu_t(acc[nt][1]) * wc.y;
            ps1 += silu_t(acc[nt][2]) * wc.x + silu_t(acc[nt][3]) * wc.y;
        }
        ps0 += __shfl_xor_sync(0xffffffffu, ps0, 1);
        ps0 += __shfl_xor_sync(0xffffffffu, ps0, 2);
        ps1 += __shfl_xor_sync(0xffffffffu, ps1, 1);
        ps1 += __shfl_xor_sync(0xffffffffu, ps1, 2);

        if (qk < 3) {
            atomicAdd(&g_aggc[r0 * 3 + qk], sCd[qr * 3 + qk] * ps0 * mk0);
            atomicAdd(&g_aggc[r1 * 3 + qk], sCd[(qr + 8) * 3 + qk] * ps1 * mk1);
        } else {
            atomicAdd(&g_cnt[r0], 1.0f);
            atomicAdd(&g_cnt[r1], 1.0f);
        }
    }
}

// ---------------- node kernel (fp32 exact) ----------------
__global__ void __launch_bounds__(256)
node_kernel(const float* __restrict__ h, const float* __restrict__ coord,
            const float* __restrict__ Wn1, const float* __restrict__ bn1,
            const float* __restrict__ Wn2, const float* __restrict__ bn2,
            float* __restrict__ out, int N, long long out_size)
{
    extern __shared__ float sm[];
    float* W1t = sm;
    float* W2t = sm + 8192;
    float* b1s = sm + 12288;
    float* b2s = sm + 12352;
    float* NinA = sm + 12416;
    float* HbA  = sm + 20608;

    int tid = threadIdx.x;
    stage_wt(W1t, Wn1, 8192, tid, 256);
    stage_wt(W2t, Wn2, 4096, tid, 256);
    if (tid < 64) { b1s[tid] = bn1[tid]; b2s[tid] = bn2[tid]; }
    __syncthreads();

    int w = tid >> 5, lane = tid & 31;
    float* Nin = NinA + w * 1024;
    float* Hb  = HbA + w * 512;
    ull b10 = pack2(b1s[2 * lane], 0.0f);
    ull b11 = pack2(b1s[2 * lane + 1], 0.0f);
    ull b20 = pack2(b2s[2 * lane], 0.0f);
    ull b21 = pack2(b2s[2 * lane + 1], 0.0f);

    float* hout = out;
    float* cout = out + (long long)N * 64;
    const bool has_coord_out = out_size >= (long long)N * 67;

    const int nGp = N / 8;
    for (int g = blockIdx.x * 8 + w; g < nGp; g += gridDim.x * 8) {
        int base = g * 8;
        __syncwarp();
#pragma unroll
        for (int i = 0; i < 8; i++) {
            int n = base + i;
            *(float2*)&Nin[i * 128 + 2 * lane]      = *(const float2*)&h[(long long)n * 64 + 2 * lane];
            *(float2*)&Nin[i * 128 + 64 + 2 * lane] = *(const float2*)&g_agg[(long long)n * 64 + 2 * lane];
            if (lane < 3 && has_coord_out) {
                float cnt = fmaxf(g_cnt[n], 1.0f);
                cout[n * 3 + lane] = coord[n * 3 + lane] + g_aggc[n * 3 + lane] / cnt;
            }
        }
        __syncwarp();

        ull a0[8], a1[8];
        gemmPK<32, 8, 128>(Nin, W1t, lane, b10, b11, a0, a1);
        __syncwarp();
#pragma unroll
        for (int i = 0; i < 8; i++)
            *(float2*)&Hb[i * 64 + 2 * lane] = make_float2(silu(fin(a0[i])), silu(fin(a1[i])));
        __syncwarp();

        gemmPK<16, 8, 64>(Hb, W2t, lane, b20, b21, a0, a1);
#pragma unroll
        for (int i = 0; i < 8; i++) {
            int n = base + i;
            *(float2*)&hout[(long long)n * 64 + 2 * lane] = make_float2(fin(a0[i]), fin(a1[i]));
        }
    }
}

extern "C" void kernel_launch(void* const* d_in, const int* in_sizes, int n_in,
                              void* d_out, int out_size) {
    const float* h     = (const float*)d_in[0];
    const float* coord = (const float*)d_in[1];
    const void*  ei    = d_in[2];
    const float* emask = (const float*)d_in[3];
    const float* We1   = (const float*)d_in[4];
    const float* be1   = (const float*)d_in[5];
    const float* We2   = (const float*)d_in[6];
    const float* be2   = (const float*)d_in[7];
    const float* Wn1   = (const float*)d_in[8];
    const float* bn1   = (const float*)d_in[9];
    const float* Wn2   = (const float*)d_in[10];
    const float* bn2   = (const float*)d_in[11];
    const float* Wc1   = (const float*)d_in[12];
    const float* bc1   = (const float*)d_in[13];
    const float* Wc2   = (const float*)d_in[14];
    float* out = (float*)d_out;

    int N = in_sizes[0] / 64;   // 40000
    int E = in_sizes[3];        // 1280000

    size_t shP = (size_t)(4096 + 4096 + 64 + 8 * 512) * sizeof(float);
    size_t shE = (size_t)SME_TOT * sizeof(float);
    size_t shN = (size_t)(8192 + 4096 + 64 + 64 + 8 * 1024 + 8 * 512) * sizeof(float);

    cudaFuncSetAttribute(pre_kernel,   cudaFuncAttributeMaxDynamicSharedMemorySize, (int)shP);
    cudaFuncSetAttribute(edge_kernel8, cudaFuncAttributeMaxDynamicSharedMemorySize, (int)shE);
    cudaFuncSetAttribute(node_kernel,  cudaFuncAttributeMaxDynamicSharedMemorySize, (int)shN);

    sniff_kernel<<<1, 256>>>((const int*)ei);
    zero_kernel<<<512, 256>>>(N);
    pre_kernel<<<296, 256, shP>>>(h, We1, be1, N);
    edge_kernel8<<<296, ETHREADS, shE>>>(coord, ei, emask,
                                         We1, We2, be2, Wc1, bc1, Wc2, E, N);
    node_kernel<<<296, 256, shN>>>(h, coord, Wn1, bn1, Wn2, bn2, out, N,
                                   (long long)out_size);
}